// round 7
// baseline (speedup 1.0000x reference)
#include <cuda_runtime.h>
#include <cuda_bf16.h>
#include <cstdint>

#define BATCH 8
#define LC    2048
#define LQ    1024
#define DIM   768
#define ODIM  1536

#define NEG_INF (-1e30f)
#define SCALE_F 0.03608439182435161f  // 1/sqrt(768)

// ---------------------------------------------------------------------------
// Scratch (__device__ globals; allocation-free rule)
// ---------------------------------------------------------------------------
__device__ __align__(16) __nv_bfloat16 g_chh[(size_t)BATCH * LC * DIM];
__device__ __align__(16) __nv_bfloat16 g_chl[(size_t)BATCH * LC * DIM];
__device__ __align__(16) __nv_bfloat16 g_qhh[(size_t)BATCH * LQ * DIM];
__device__ __align__(16) __nv_bfloat16 g_qhl[(size_t)BATCH * LQ * DIM];
__device__ __align__(16) __nv_bfloat16 g_qth[(size_t)BATCH * DIM * LQ];  // qh^T [b, d, q]
__device__ __align__(16) __nv_bfloat16 g_qtl[(size_t)BATCH * DIM * LQ];
__device__ __align__(16) __nv_bfloat16 g_wh[DIM * DIM];
__device__ __align__(16) __nv_bfloat16 g_wl[DIM * DIM];
__device__ __align__(16) __nv_bfloat16 g_qryh[(size_t)BATCH * LQ * DIM];
__device__ __align__(16) __nv_bfloat16 g_qryl[(size_t)BATCH * LQ * DIM];
__device__ __align__(16) float         g_scores[(size_t)BATCH * LC * LQ];
__device__ __align__(16) __nv_bfloat16 g_ph[(size_t)BATCH * LC * LQ];
__device__ __align__(16) __nv_bfloat16 g_pl[(size_t)BATCH * LC * LQ];

// ---------------------------------------------------------------------------
// helpers
// ---------------------------------------------------------------------------
static __device__ __forceinline__ uint32_t smem_u32(const void* p) {
    uint32_t r;
    asm("{ .reg .u64 t; cvta.to.shared.u64 t, %1; cvt.u32.u64 %0, t; }"
        : "=r"(r) : "l"(p));
    return r;
}

static __device__ __forceinline__ void cp16(uint32_t dst, const void* src) {
    asm volatile("cp.async.cg.shared.global [%0], [%1], 16;" :: "r"(dst), "l"(src));
}

static __device__ __forceinline__ void split2(float x, __nv_bfloat16& h, __nv_bfloat16& l) {
    h = __float2bfloat16_rn(x);
    l = __float2bfloat16_rn(x - __bfloat162float(h));
}
static __device__ __forceinline__ uint32_t packbf(__nv_bfloat16 a, __nv_bfloat16 b) {
    __nv_bfloat162 t = __halves2bfloat162(a, b);
    return *reinterpret_cast<uint32_t*>(&t);
}

#define LDSM_X4(r0, r1, r2, r3, addr) \
    asm volatile("ldmatrix.sync.aligned.m8n8.x4.shared.b16 {%0,%1,%2,%3}, [%4];" \
                 : "=r"(r0), "=r"(r1), "=r"(r2), "=r"(r3) : "r"(addr))

#define MMA16816(d, a, b) \
    asm volatile("mma.sync.aligned.m16n8k16.row.col.f32.bf16.bf16.f32 " \
                 "{%0,%1,%2,%3}, {%4,%5,%6,%7}, {%8,%9}, {%0,%1,%2,%3};" \
                 : "+f"((d)[0]), "+f"((d)[1]), "+f"((d)[2]), "+f"((d)[3]) \
                 : "r"((a)[0]), "r"((a)[1]), "r"((a)[2]), "r"((a)[3]), \
                   "r"((b)[0]), "r"((b)[1]))

// ---------------------------------------------------------------------------
// SMEM: 3 stages x (A tile 16KB + B tile 16KB).
// Tile: 128 rows x 128B; each row = 32 hi bf16 | 32 lo bf16 for a 32-k chunk.
// SW128-style XOR swizzle, conflict-free for ldmatrix.
// ---------------------------------------------------------------------------
#define CHUNK    32
#define TILE_B   16384
#define STAGE_B  (2 * TILE_B)
#define NSTAGE   3
#define SMEM_DYN (NSTAGE * STAGE_B)

static __device__ __forceinline__ uint32_t swz(uint32_t row, uint32_t kbyte) {
    return (row * 128 + kbyte) ^ ((row & 7) << 4);
}

static __device__ __forceinline__ void load_chunk(
    uint32_t sb,
    const __nv_bfloat16* __restrict__ Ah, const __nv_bfloat16* __restrict__ Al, int ldA,
    const __nv_bfloat16* __restrict__ Bh, const __nv_bfloat16* __restrict__ Bl, int ldB,
    int k0, int tid) {
    // A tile: 1024 x 16B chunks over 256 threads (4 each)
    #pragma unroll
    for (int i = 0; i < 4; i++) {
        int idx = tid + i * 256;
        int row = idx >> 3, seg = idx & 7;  // seg 0-3: hi, 4-7: lo
        const __nv_bfloat16* s = (seg < 4)
            ? (Ah + (size_t)row * ldA + k0 + seg * 8)
            : (Al + (size_t)row * ldA + k0 + (seg - 4) * 8);
        cp16(sb + swz(row, seg * 16), (const void*)s);
    }
    // B tile
    #pragma unroll
    for (int i = 0; i < 4; i++) {
        int idx = tid + i * 256;
        int row = idx >> 3, seg = idx & 7;
        const __nv_bfloat16* s = (seg < 4)
            ? (Bh + (size_t)row * ldB + k0 + seg * 8)
            : (Bl + (size_t)row * ldB + k0 + (seg - 4) * 8);
        cp16(sb + TILE_B + swz(row, seg * 16), (const void*)s);
    }
    asm volatile("cp.async.commit_group;" ::: "memory");
}

// One 32-k chunk for this warp (tile 64x32), 3-pass bf16 split.
static __device__ __forceinline__ void compute_chunk(uint32_t sb, int wm, int wn, int lane,
                                                     float acc[4][4][4]) {
    const uint32_t tA = sb, tB = sb + TILE_B;
    #pragma unroll
    for (int ks = 0; ks < 2; ks++) {
        const uint32_t abyte = ks * 32 + ((lane >> 4) << 4);
        const uint32_t arow = wm * 64 + (lane & 15);
        uint32_t ah[4][4], al[4][4];
        #pragma unroll
        for (int tm = 0; tm < 4; tm++) {
            LDSM_X4(ah[tm][0], ah[tm][1], ah[tm][2], ah[tm][3],
                    tA + swz(arow + tm * 16, abyte));
            LDSM_X4(al[tm][0], al[tm][1], al[tm][2], al[tm][3],
                    tA + swz(arow + tm * 16, 64 + abyte));
        }
        const uint32_t brow = wn * 32 + (lane & 7) + ((lane >> 4) << 3);
        const uint32_t bbyte = ks * 32 + (((lane >> 3) & 1) << 4);
        uint32_t b[4][2];
        // B hi: ah*bh and al*bh
        #pragma unroll
        for (int tp = 0; tp < 2; tp++) {
            uint32_t t0, t1, t2, t3;
            LDSM_X4(t0, t1, t2, t3, tB + swz(brow + tp * 16, bbyte));
            b[tp * 2][0] = t0; b[tp * 2][1] = t1;
            b[tp * 2 + 1][0] = t2; b[tp * 2 + 1][1] = t3;
        }
        #pragma unroll
        for (int tm = 0; tm < 4; tm++)
            #pragma unroll
            for (int tn = 0; tn < 4; tn++) {
                MMA16816(acc[tm][tn], ah[tm], b[tn]);
                MMA16816(acc[tm][tn], al[tm], b[tn]);
            }
        // B lo: ah*bl (reuse b regs)
        #pragma unroll
        for (int tp = 0; tp < 2; tp++) {
            uint32_t t0, t1, t2, t3;
            LDSM_X4(t0, t1, t2, t3, tB + swz(brow + tp * 16, 64 + bbyte));
            b[tp * 2][0] = t0; b[tp * 2][1] = t1;
            b[tp * 2 + 1][0] = t2; b[tp * 2 + 1][1] = t3;
        }
        #pragma unroll
        for (int tm = 0; tm < 4; tm++)
            #pragma unroll
            for (int tn = 0; tn < 4; tn++)
                MMA16816(acc[tm][tn], ah[tm], b[tn]);
    }
}

static __device__ __forceinline__ void mainloop(
    const __nv_bfloat16* __restrict__ Ah, const __nv_bfloat16* __restrict__ Al, int ldA,
    const __nv_bfloat16* __restrict__ Bh, const __nv_bfloat16* __restrict__ Bl, int ldB,
    int nk, float acc[4][4][4]) {
    extern __shared__ char smem[];
    const uint32_t sb = smem_u32(smem);
    const int tid = threadIdx.x, lane = tid & 31, wid = tid >> 5;
    const int wm = wid & 1, wn = wid >> 1;

    load_chunk(sb, Ah, Al, ldA, Bh, Bl, ldB, 0, tid);
    load_chunk(sb + STAGE_B, Ah, Al, ldA, Bh, Bl, ldB, CHUNK, tid);

    for (int k = 0; k < nk; k++) {
        if (k + 2 < nk) {
            load_chunk(sb + ((k + 2) % 3) * STAGE_B, Ah, Al, ldA, Bh, Bl, ldB,
                       (k + 2) * CHUNK, tid);
            asm volatile("cp.async.wait_group 2;" ::: "memory");
        } else if (k + 1 < nk) {
            asm volatile("cp.async.wait_group 1;" ::: "memory");
        } else {
            asm volatile("cp.async.wait_group 0;" ::: "memory");
        }
        __syncthreads();
        compute_chunk(sb + (k % 3) * STAGE_B, wm, wn, lane, acc);
        __syncthreads();
    }
}

// ---------------------------------------------------------------------------
// GEMM 1: query[m, e] = qh[m, :] . W[e, :] + b[e]; bf16 hi/lo out. grid (6, 64)
// ---------------------------------------------------------------------------
__global__ __launch_bounds__(256, 2) void k_gemm_query(const float* __restrict__ bias) {
    float acc[4][4][4] = {};
    const size_t aoff = (size_t)blockIdx.y * 128 * DIM;
    const size_t boff = (size_t)blockIdx.x * 128 * DIM;
    mainloop(g_qhh + aoff, g_qhl + aoff, DIM, g_wh + boff, g_wl + boff, DIM, DIM / CHUNK, acc);

    const int lane = threadIdx.x & 31, wid = threadIdx.x >> 5;
    const int wm = wid & 1, wn = wid >> 1;
    const int gr = lane >> 2, gc = (lane & 3) * 2;
    const int row0 = blockIdx.y * 128 + wm * 64, col0 = blockIdx.x * 128 + wn * 32;
    #pragma unroll
    for (int tn = 0; tn < 4; tn++) {
        const int c = col0 + tn * 8 + gc;
        const float2 bb = *reinterpret_cast<const float2*>(bias + c);
        #pragma unroll
        for (int tm = 0; tm < 4; tm++)
            #pragma unroll
            for (int hf = 0; hf < 2; hf++) {
                const int r = row0 + tm * 16 + gr + hf * 8;
                float v0 = acc[tm][tn][hf * 2 + 0] + bb.x;
                float v1 = acc[tm][tn][hf * 2 + 1] + bb.y;
                __nv_bfloat16 h0, l0, h1, l1;
                split2(v0, h0, l0);
                split2(v1, h1, l1);
                const size_t o = (size_t)r * DIM + c;
                *reinterpret_cast<uint32_t*>(&g_qryh[o]) = packbf(h0, h1);
                *reinterpret_cast<uint32_t*>(&g_qryl[o]) = packbf(l0, l1);
            }
    }
}

// ---------------------------------------------------------------------------
// GEMM 2: scores[b][c, q] = SCALE * ch[b,c,:] . query[b,q,:]; mask -> -1e30
// grid (8, 16, 8)
// ---------------------------------------------------------------------------
__global__ __launch_bounds__(256, 2) void k_gemm_scores(const int* __restrict__ qmask) {
    float acc[4][4][4] = {};
    const int z = blockIdx.z;
    const size_t aoff = (size_t)z * LC * DIM + (size_t)blockIdx.y * 128 * DIM;
    const size_t boff = (size_t)z * LQ * DIM + (size_t)blockIdx.x * 128 * DIM;
    mainloop(g_chh + aoff, g_chl + aoff, DIM, g_qryh + boff, g_qryl + boff, DIM, DIM / CHUNK, acc);

    const int lane = threadIdx.x & 31, wid = threadIdx.x >> 5;
    const int wm = wid & 1, wn = wid >> 1;
    const int gr = lane >> 2, gc = (lane & 3) * 2;
    const int row0 = blockIdx.y * 128 + wm * 64, col0 = blockIdx.x * 128 + wn * 32;
    float* sbase = g_scores + (size_t)z * LC * LQ;
    const int* mrow = qmask + (size_t)z * LQ;
    #pragma unroll
    for (int tn = 0; tn < 4; tn++) {
        const int c = col0 + tn * 8 + gc;
        const int2 mk = *reinterpret_cast<const int2*>(mrow + c);
        #pragma unroll
        for (int tm = 0; tm < 4; tm++)
            #pragma unroll
            for (int hf = 0; hf < 2; hf++) {
                const int r = row0 + tm * 16 + gr + hf * 8;
                float2 v;
                v.x = mk.x ? acc[tm][tn][hf * 2 + 0] * SCALE_F : NEG_INF;
                v.y = mk.y ? acc[tm][tn][hf * 2 + 1] * SCALE_F : NEG_INF;
                *reinterpret_cast<float2*>(sbase + (size_t)r * LQ + c) = v;
            }
    }
}

// ---------------------------------------------------------------------------
// GEMM 3: attn[b][c, d] = P[b][c, :] . qhT[b][d, :]  (K=LQ). grid (6, 16, 8)
// ---------------------------------------------------------------------------
__global__ __launch_bounds__(256, 2) void k_gemm_out(float* __restrict__ out) {
    float acc[4][4][4] = {};
    const int z = blockIdx.z;
    const size_t aoff = (size_t)z * LC * LQ + (size_t)blockIdx.y * 128 * LQ;
    const size_t boff = (size_t)z * DIM * LQ + (size_t)blockIdx.x * 128 * LQ;
    mainloop(g_ph + aoff, g_pl + aoff, LQ, g_qth + boff, g_qtl + boff, LQ, LQ / CHUNK, acc);

    const int lane = threadIdx.x & 31, wid = threadIdx.x >> 5;
    const int wm = wid & 1, wn = wid >> 1;
    const int gr = lane >> 2, gc = (lane & 3) * 2;
    const int row0 = blockIdx.y * 128 + wm * 64, col0 = blockIdx.x * 128 + wn * 32;
    float* obase = out + (size_t)z * LC * ODIM + DIM;
    #pragma unroll
    for (int tn = 0; tn < 4; tn++) {
        const int c = col0 + tn * 8 + gc;
        #pragma unroll
        for (int tm = 0; tm < 4; tm++)
            #pragma unroll
            for (int hf = 0; hf < 2; hf++) {
                const int r = row0 + tm * 16 + gr + hf * 8;
                float2 v = make_float2(acc[tm][tn][hf * 2 + 0], acc[tm][tn][hf * 2 + 1]);
                *reinterpret_cast<float2*>(obase + (size_t)r * ODIM + c) = v;
            }
    }
}

// ---------------------------------------------------------------------------
// Prep: ch -> out[0:768] copy + bf16 hi/lo split (one read pass)
// ---------------------------------------------------------------------------
__global__ __launch_bounds__(256) void k_prep_ch(const float* __restrict__ ch,
                                                 float* __restrict__ out) {
    const size_t total4 = (size_t)BATCH * LC * (DIM / 4);
    for (size_t i = (size_t)blockIdx.x * blockDim.x + threadIdx.x; i < total4;
         i += (size_t)gridDim.x * blockDim.x) {
        float4 x = reinterpret_cast<const float4*>(ch)[i];
        size_t row = i / (DIM / 4);
        size_t d4 = i % (DIM / 4);
        reinterpret_cast<float4*>(out)[row * (ODIM / 4) + d4] = x;
        __nv_bfloat16 h0, h1, h2, h3, l0, l1, l2, l3;
        split2(x.x, h0, l0); split2(x.y, h1, l1);
        split2(x.z, h2, l2); split2(x.w, h3, l3);
        reinterpret_cast<uint2*>(g_chh)[i] = make_uint2(packbf(h0, h1), packbf(h2, h3));
        reinterpret_cast<uint2*>(g_chl)[i] = make_uint2(packbf(l0, l1), packbf(l2, l3));
    }
}

// ---------------------------------------------------------------------------
// Prep: qh -> row-major split (qhh/qhl) + transposed split (qth/qtl)
// grid (24, 32, 8), block (32, 8)
// ---------------------------------------------------------------------------
__global__ __launch_bounds__(256) void k_prep_q(const float* __restrict__ qh) {
    __shared__ float t[32][33];
    int z = blockIdx.z;
    int d0 = blockIdx.x * 32, q0 = blockIdx.y * 32;
    const float* src = qh + (size_t)z * LQ * DIM;
    int tx = threadIdx.x, ty = threadIdx.y;
    __nv_bfloat16* rh = g_qhh + (size_t)z * LQ * DIM;
    __nv_bfloat16* rl = g_qhl + (size_t)z * LQ * DIM;
    #pragma unroll
    for (int i = 0; i < 4; i++) {
        int q = q0 + ty + 8 * i;
        float v = src[(size_t)q * DIM + d0 + tx];
        t[ty + 8 * i][tx] = v;
        __nv_bfloat16 h, l;
        split2(v, h, l);
        size_t o = (size_t)q * DIM + d0 + tx;
        rh[o] = h;
        rl[o] = l;
    }
    __syncthreads();
    __nv_bfloat16* dh = g_qth + (size_t)z * DIM * LQ;
    __nv_bfloat16* dl = g_qtl + (size_t)z * DIM * LQ;
    #pragma unroll
    for (int i = 0; i < 4; i++) {
        float v = t[tx][ty + 8 * i];
        __nv_bfloat16 h, l;
        split2(v, h, l);
        size_t o = (size_t)(d0 + ty + 8 * i) * LQ + q0 + tx;
        dh[o] = h;
        dl[o] = l;
    }
}

// ---------------------------------------------------------------------------
// W split
// ---------------------------------------------------------------------------
__global__ __launch_bounds__(256) void k_split_w(const float* __restrict__ src, int n4) {
    int i = blockIdx.x * blockDim.x + threadIdx.x;
    if (i >= n4) return;
    float4 x = reinterpret_cast<const float4*>(src)[i];
    __nv_bfloat16 h0, h1, h2, h3, l0, l1, l2, l3;
    split2(x.x, h0, l0); split2(x.y, h1, l1);
    split2(x.z, h2, l2); split2(x.w, h3, l3);
    reinterpret_cast<uint2*>(g_wh)[i] = make_uint2(packbf(h0, h1), packbf(h2, h3));
    reinterpret_cast<uint2*>(g_wl)[i] = make_uint2(packbf(l0, l1), packbf(l2, l3));
}

// ---------------------------------------------------------------------------
// Row softmax over Lq=1024; fp32 in, P as bf16 hi/lo out. grid 16384 x 256
// ---------------------------------------------------------------------------
__global__ __launch_bounds__(256) void k_softmax() {
    const size_t rowoff = (size_t)blockIdx.x * LQ;
    const float* p = g_scores + rowoff;
    const int t = threadIdx.x;
    float4 v = reinterpret_cast<const float4*>(p)[t];

    __shared__ float red[8];
    float m = fmaxf(fmaxf(v.x, v.y), fmaxf(v.z, v.w));
    #pragma unroll
    for (int o = 16; o; o >>= 1) m = fmaxf(m, __shfl_xor_sync(0xffffffffu, m, o));
    if ((t & 31) == 0) red[t >> 5] = m;
    __syncthreads();
    m = red[0];
    #pragma unroll
    for (int w = 1; w < 8; w++) m = fmaxf(m, red[w]);
    __syncthreads();

    v.x = __expf(v.x - m); v.y = __expf(v.y - m);
    v.z = __expf(v.z - m); v.w = __expf(v.w - m);
    float s = v.x + v.y + v.z + v.w;
    #pragma unroll
    for (int o = 16; o; o >>= 1) s += __shfl_xor_sync(0xffffffffu, s, o);
    if ((t & 31) == 0) red[t >> 5] = s;
    __syncthreads();
    s = red[0];
    #pragma unroll
    for (int w = 1; w < 8; w++) s += red[w];

    float inv = 1.0f / s;
    v.x *= inv; v.y *= inv; v.z *= inv; v.w *= inv;

    __nv_bfloat16 h0, h1, h2, h3, l0, l1, l2, l3;
    split2(v.x, h0, l0); split2(v.y, h1, l1);
    split2(v.z, h2, l2); split2(v.w, h3, l3);
    reinterpret_cast<uint2*>(g_ph + rowoff)[t] = make_uint2(packbf(h0, h1), packbf(h2, h3));
    reinterpret_cast<uint2*>(g_pl + rowoff)[t] = make_uint2(packbf(l0, l1), packbf(l2, l3));
}

// ---------------------------------------------------------------------------
extern "C" void kernel_launch(void* const* d_in, const int* in_sizes, int n_in,
                              void* d_out, int out_size) {
    const float* ch    = (const float*)d_in[0];
    const float* qh    = (const float*)d_in[2];
    const int*   qmask = (const int*)d_in[3];
    const float* W     = (const float*)d_in[4];
    const float* bias  = (const float*)d_in[5];
    float*       out   = (float*)d_out;

    cudaFuncSetAttribute(k_gemm_query, cudaFuncAttributeMaxDynamicSharedMemorySize, SMEM_DYN);
    cudaFuncSetAttribute(k_gemm_scores, cudaFuncAttributeMaxDynamicSharedMemorySize, SMEM_DYN);
    cudaFuncSetAttribute(k_gemm_out, cudaFuncAttributeMaxDynamicSharedMemorySize, SMEM_DYN);

    int n4_w = DIM * DIM / 4;
    k_prep_ch<<<1184, 256>>>(ch, out);
    k_prep_q<<<dim3(DIM / 32, LQ / 32, BATCH), dim3(32, 8)>>>(qh);
    k_split_w<<<(n4_w + 255) / 256, 256>>>(W, n4_w);

    k_gemm_query<<<dim3(DIM / 128, BATCH * LQ / 128), 256, SMEM_DYN>>>(bias);
    k_gemm_scores<<<dim3(LQ / 128, LC / 128, BATCH), 256, SMEM_DYN>>>(qmask);
    k_softmax<<<BATCH * LC, 256>>>();
    k_gemm_out<<<dim3(DIM / 128, LC / 128, BATCH), 256, SMEM_DYN>>>(out);
}

// round 10
// speedup vs baseline: 1.3401x; 1.3401x over previous
#include <cuda_runtime.h>
#include <cuda_fp16.h>
#include <cstdint>

#define BATCH 8
#define LC    2048
#define LQ    1024
#define DIM   768
#define ODIM  1536

#define NEG_INF (-1e30f)
#define SCALE_F 0.03608439182435161f  // 1/sqrt(768)

// ---------------------------------------------------------------------------
// Scratch (__device__ globals; allocation-free rule). fp16 operands.
// ---------------------------------------------------------------------------
__device__ __align__(16) __half g_chh[(size_t)BATCH * LC * DIM];   // ch single
__device__ __align__(16) __half g_qhh[(size_t)BATCH * LQ * DIM];   // qh hi
__device__ __align__(16) __half g_qhl[(size_t)BATCH * LQ * DIM];   // qh lo
__device__ __align__(16) __half g_qth[(size_t)BATCH * DIM * LQ];   // qh^T hi
__device__ __align__(16) __half g_qtl[(size_t)BATCH * DIM * LQ];   // qh^T lo
__device__ __align__(16) __half g_wh[DIM * DIM];
__device__ __align__(16) __half g_wl[DIM * DIM];
__device__ __align__(16) __half g_qryh[(size_t)BATCH * LQ * DIM];
__device__ __align__(16) __half g_qryl[(size_t)BATCH * LQ * DIM];
__device__ __align__(16) float  g_scores[(size_t)BATCH * LC * LQ];
__device__ __align__(16) __half g_ph[(size_t)BATCH * LC * LQ];     // P single

// ---------------------------------------------------------------------------
// helpers
// ---------------------------------------------------------------------------
static __device__ __forceinline__ uint32_t smem_u32(const void* p) {
    uint32_t r;
    asm("{ .reg .u64 t; cvta.to.shared.u64 t, %1; cvt.u32.u64 %0, t; }"
        : "=r"(r) : "l"(p));
    return r;
}
static __device__ __forceinline__ void cp16(uint32_t dst, const void* src) {
    asm volatile("cp.async.cg.shared.global [%0], [%1], 16;" :: "r"(dst), "l"(src));
}
static __device__ __forceinline__ void split2h(float x, __half& h, __half& l) {
    h = __float2half_rn(x);
    l = __float2half_rn(x - __half2float(h));
}
static __device__ __forceinline__ uint32_t packh(__half a, __half b) {
    __half2 t = __halves2half2(a, b);
    return *reinterpret_cast<uint32_t*>(&t);
}

#define LDSM_X4(r0, r1, r2, r3, addr) \
    asm volatile("ldmatrix.sync.aligned.m8n8.x4.shared.b16 {%0,%1,%2,%3}, [%4];" \
                 : "=r"(r0), "=r"(r1), "=r"(r2), "=r"(r3) : "r"(addr))

#define MMA16816(d, a, b) \
    asm volatile("mma.sync.aligned.m16n8k16.row.col.f32.f16.f16.f32 " \
                 "{%0,%1,%2,%3}, {%4,%5,%6,%7}, {%8,%9}, {%0,%1,%2,%3};" \
                 : "+f"((d)[0]), "+f"((d)[1]), "+f"((d)[2]), "+f"((d)[3]) \
                 : "r"((a)[0]), "r"((a)[1]), "r"((a)[2]), "r"((a)[3]), \
                   "r"((b)[0]), "r"((b)[1]))

// ---------------------------------------------------------------------------
// Tiles (k-chunk = 32 fp16):
//   split tile : 128 rows x 128B (32 hi fp16 | 32 lo fp16), swz128
//   single tile: 128 rows x  64B (32 fp16),                swz64
// ---------------------------------------------------------------------------
#define CHUNK 32
#define STILE_B 16384   // split tile bytes
#define NTILE_B 8192    // single tile bytes

static __device__ __forceinline__ uint32_t swz128(uint32_t row, uint32_t kb) {
    return (row * 128 + kb) ^ ((row & 7) << 4);
}
static __device__ __forceinline__ uint32_t swz64(uint32_t row, uint32_t kb) {
    return row * 64 + (kb ^ (((row >> 1) & 3) << 4));
}

// GEMM1 stage: A split (16KB) + B split (16KB) = 32KB, 3 stages = 96KB
#define STAGE1_B (2 * STILE_B)
// GEMM2/3 stage: A single (8KB) + B split (16KB) = 24KB, 4 stages = 96KB
#define STAGE2_B (NTILE_B + STILE_B)
#define SMEM_DYN 98304

// ---- loaders ----
static __device__ __forceinline__ void load_split(uint32_t tb,
    const __half* __restrict__ H, const __half* __restrict__ L, int ld, int k0, int tid) {
    #pragma unroll
    for (int i = 0; i < 4; i++) {
        int idx = tid + i * 256;            // 1024 segs: 128 rows x 8 (0-3 hi, 4-7 lo)
        int row = idx >> 3, seg = idx & 7;
        const __half* s = (seg < 4) ? (H + (size_t)row * ld + k0 + seg * 8)
                                    : (L + (size_t)row * ld + k0 + (seg - 4) * 8);
        cp16(tb + swz128(row, seg * 16), (const void*)s);
    }
}
static __device__ __forceinline__ void load_single(uint32_t tb,
    const __half* __restrict__ H, int ld, int k0, int tid) {
    #pragma unroll
    for (int i = 0; i < 2; i++) {
        int idx = tid + i * 256;            // 512 segs: 128 rows x 4
        int row = idx >> 2, seg = idx & 3;
        cp16(tb + swz64(row, seg * 16), (const void*)(H + (size_t)row * ld + k0 + seg * 8));
    }
}

// ---- compute: 3-pass (A split + B split), warp tile 64x32 ----
static __device__ __forceinline__ void compute3(uint32_t sb, int wm, int wn, int lane,
                                                float acc[4][4][4]) {
    const uint32_t tA = sb, tB = sb + STILE_B;
    #pragma unroll
    for (int ks = 0; ks < 2; ks++) {
        const uint32_t akb = ks * 32 + ((lane >> 4) << 4);
        const uint32_t arow = wm * 64 + (lane & 15);
        uint32_t ah[4][4], al[4][4];
        #pragma unroll
        for (int tm = 0; tm < 4; tm++) {
            LDSM_X4(ah[tm][0], ah[tm][1], ah[tm][2], ah[tm][3], tA + swz128(arow + tm * 16, akb));
            LDSM_X4(al[tm][0], al[tm][1], al[tm][2], al[tm][3], tA + swz128(arow + tm * 16, 64 + akb));
        }
        const uint32_t brow = wn * 32 + (lane & 7) + ((lane >> 4) << 3);
        const uint32_t bkb = ks * 32 + (((lane >> 3) & 1) << 4);
        uint32_t b[4][2];
        #pragma unroll
        for (int tp = 0; tp < 2; tp++) {
            uint32_t t0, t1, t2, t3;
            LDSM_X4(t0, t1, t2, t3, tB + swz128(brow + tp * 16, bkb));
            b[tp * 2][0] = t0; b[tp * 2][1] = t1;
            b[tp * 2 + 1][0] = t2; b[tp * 2 + 1][1] = t3;
        }
        #pragma unroll
        for (int tm = 0; tm < 4; tm++)
            #pragma unroll
            for (int tn = 0; tn < 4; tn++) {
                MMA16816(acc[tm][tn], ah[tm], b[tn]);
                MMA16816(acc[tm][tn], al[tm], b[tn]);
            }
        #pragma unroll
        for (int tp = 0; tp < 2; tp++) {
            uint32_t t0, t1, t2, t3;
            LDSM_X4(t0, t1, t2, t3, tB + swz128(brow + tp * 16, 64 + bkb));
            b[tp * 2][0] = t0; b[tp * 2][1] = t1;
            b[tp * 2 + 1][0] = t2; b[tp * 2 + 1][1] = t3;
        }
        #pragma unroll
        for (int tm = 0; tm < 4; tm++)
            #pragma unroll
            for (int tn = 0; tn < 4; tn++)
                MMA16816(acc[tm][tn], ah[tm], b[tn]);
    }
}

// ---- compute: 2-pass (A single + B split) ----
static __device__ __forceinline__ void compute2(uint32_t sb, int wm, int wn, int lane,
                                                float acc[4][4][4]) {
    const uint32_t tA = sb, tB = sb + NTILE_B;
    #pragma unroll
    for (int ks = 0; ks < 2; ks++) {
        const uint32_t akb = ks * 32 + ((lane >> 4) << 4);
        const uint32_t arow = wm * 64 + (lane & 15);
        uint32_t a[4][4];
        #pragma unroll
        for (int tm = 0; tm < 4; tm++)
            LDSM_X4(a[tm][0], a[tm][1], a[tm][2], a[tm][3], tA + swz64(arow + tm * 16, akb));
        const uint32_t brow = wn * 32 + (lane & 7) + ((lane >> 4) << 3);
        const uint32_t bkb = ks * 32 + (((lane >> 3) & 1) << 4);
        uint32_t b[4][2];
        #pragma unroll
        for (int tp = 0; tp < 2; tp++) {
            uint32_t t0, t1, t2, t3;
            LDSM_X4(t0, t1, t2, t3, tB + swz128(brow + tp * 16, bkb));
            b[tp * 2][0] = t0; b[tp * 2][1] = t1;
            b[tp * 2 + 1][0] = t2; b[tp * 2 + 1][1] = t3;
        }
        #pragma unroll
        for (int tm = 0; tm < 4; tm++)
            #pragma unroll
            for (int tn = 0; tn < 4; tn++)
                MMA16816(acc[tm][tn], a[tm], b[tn]);
        #pragma unroll
        for (int tp = 0; tp < 2; tp++) {
            uint32_t t0, t1, t2, t3;
            LDSM_X4(t0, t1, t2, t3, tB + swz128(brow + tp * 16, 64 + bkb));
            b[tp * 2][0] = t0; b[tp * 2][1] = t1;
            b[tp * 2 + 1][0] = t2; b[tp * 2 + 1][1] = t3;
        }
        #pragma unroll
        for (int tm = 0; tm < 4; tm++)
            #pragma unroll
            for (int tn = 0; tn < 4; tn++)
                MMA16816(acc[tm][tn], a[tm], b[tn]);
    }
}

// ---- mainloops: single __syncthreads per iteration ----
// order: wait(own group k) -> barrier (publish + free stage) -> prefetch -> compute
static __device__ __forceinline__ void mainloop3(
    const __half* Ah, const __half* Al, int ldA,
    const __half* Bh, const __half* Bl, int ldB, int nk, float acc[4][4][4]) {
    extern __shared__ char smem[];
    const uint32_t sb = smem_u32(smem);
    const int tid = threadIdx.x, lane = tid & 31, wid = tid >> 5;
    const int wm = wid & 1, wn = wid >> 1;

    load_split(sb, Ah, Al, ldA, 0, tid);
    load_split(sb + STILE_B, Bh, Bl, ldB, 0, tid);
    asm volatile("cp.async.commit_group;" ::: "memory");
    load_split(sb + STAGE1_B, Ah, Al, ldA, CHUNK, tid);
    load_split(sb + STAGE1_B + STILE_B, Bh, Bl, ldB, CHUNK, tid);
    asm volatile("cp.async.commit_group;" ::: "memory");

    for (int k = 0; k < nk; k++) {
        if (k + 1 < nk) asm volatile("cp.async.wait_group 1;" ::: "memory");
        else            asm volatile("cp.async.wait_group 0;" ::: "memory");
        __syncthreads();
        if (k + 2 < nk) {
            uint32_t st = sb + ((k + 2) % 3) * STAGE1_B;
            load_split(st, Ah, Al, ldA, (k + 2) * CHUNK, tid);
            load_split(st + STILE_B, Bh, Bl, ldB, (k + 2) * CHUNK, tid);
            asm volatile("cp.async.commit_group;" ::: "memory");
        }
        compute3(sb + (k % 3) * STAGE1_B, wm, wn, lane, acc);
    }
}

static __device__ __forceinline__ void mainloop2(
    const __half* A, int ldA,
    const __half* Bh, const __half* Bl, int ldB, int nk, float acc[4][4][4]) {
    extern __shared__ char smem[];
    const uint32_t sb = smem_u32(smem);
    const int tid = threadIdx.x, lane = tid & 31, wid = tid >> 5;
    const int wm = wid & 1, wn = wid >> 1;

    #pragma unroll
    for (int p = 0; p < 3; p++) {
        uint32_t st = sb + p * STAGE2_B;
        load_single(st, A, ldA, p * CHUNK, tid);
        load_split(st + NTILE_B, Bh, Bl, ldB, p * CHUNK, tid);
        asm volatile("cp.async.commit_group;" ::: "memory");
    }
    for (int k = 0; k < nk; k++) {
        if (k + 2 < nk)      asm volatile("cp.async.wait_group 2;" ::: "memory");
        else if (k + 1 < nk) asm volatile("cp.async.wait_group 1;" ::: "memory");
        else                 asm volatile("cp.async.wait_group 0;" ::: "memory");
        __syncthreads();
        if (k + 3 < nk) {
            uint32_t st = sb + ((k + 3) & 3) * STAGE2_B;
            load_single(st, A, ldA, (k + 3) * CHUNK, tid);
            load_split(st + NTILE_B, Bh, Bl, ldB, (k + 3) * CHUNK, tid);
            asm volatile("cp.async.commit_group;" ::: "memory");
        }
        compute2(sb + (k & 3) * STAGE2_B, wm, wn, lane, acc);
    }
}

// ---------------------------------------------------------------------------
// GEMM 1: query[m,e] = qh[m,:] . W[e,:] + b[e]; 3-pass; fp16 hi/lo out. grid (6, 64)
// ---------------------------------------------------------------------------
__global__ __launch_bounds__(256, 2) void k_gemm_query(const float* __restrict__ bias) {
    float acc[4][4][4] = {};
    const size_t aoff = (size_t)blockIdx.y * 128 * DIM;
    const size_t boff = (size_t)blockIdx.x * 128 * DIM;
    mainloop3(g_qhh + aoff, g_qhl + aoff, DIM, g_wh + boff, g_wl + boff, DIM, DIM / CHUNK, acc);

    const int lane = threadIdx.x & 31, wid = threadIdx.x >> 5;
    const int wm = wid & 1, wn = wid >> 1;
    const int gr = lane >> 2, gc = (lane & 3) * 2;
    const int row0 = blockIdx.y * 128 + wm * 64, col0 = blockIdx.x * 128 + wn * 32;
    #pragma unroll
    for (int tn = 0; tn < 4; tn++) {
        const int c = col0 + tn * 8 + gc;
        const float2 bb = *reinterpret_cast<const float2*>(bias + c);
        #pragma unroll
        for (int tm = 0; tm < 4; tm++)
            #pragma unroll
            for (int hf = 0; hf < 2; hf++) {
                const int r = row0 + tm * 16 + gr + hf * 8;
                float v0 = acc[tm][tn][hf * 2 + 0] + bb.x;
                float v1 = acc[tm][tn][hf * 2 + 1] + bb.y;
                __half h0, l0, h1, l1;
                split2h(v0, h0, l0);
                split2h(v1, h1, l1);
                const size_t o = (size_t)r * DIM + c;
                *reinterpret_cast<uint32_t*>(&g_qryh[o]) = packh(h0, h1);
                *reinterpret_cast<uint32_t*>(&g_qryl[o]) = packh(l0, l1);
            }
    }
}

// ---------------------------------------------------------------------------
// GEMM 2: scores = SCALE * ch . query^T; mask -> -1e30; 2-pass. grid (8, 16, 8)
// ---------------------------------------------------------------------------
__global__ __launch_bounds__(256, 2) void k_gemm_scores(const int* __restrict__ qmask) {
    float acc[4][4][4] = {};
    const int z = blockIdx.z;
    const size_t aoff = (size_t)z * LC * DIM + (size_t)blockIdx.y * 128 * DIM;
    const size_t boff = (size_t)z * LQ * DIM + (size_t)blockIdx.x * 128 * DIM;
    mainloop2(g_chh + aoff, DIM, g_qryh + boff, g_qryl + boff, DIM, DIM / CHUNK, acc);

    const int lane = threadIdx.x & 31, wid = threadIdx.x >> 5;
    const int wm = wid & 1, wn = wid >> 1;
    const int gr = lane >> 2, gc = (lane & 3) * 2;
    const int row0 = blockIdx.y * 128 + wm * 64, col0 = blockIdx.x * 128 + wn * 32;
    float* sbase = g_scores + (size_t)z * LC * LQ;
    const int* mrow = qmask + (size_t)z * LQ;
    #pragma unroll
    for (int tn = 0; tn < 4; tn++) {
        const int c = col0 + tn * 8 + gc;
        const int2 mk = *reinterpret_cast<const int2*>(mrow + c);
        #pragma unroll
        for (int tm = 0; tm < 4; tm++)
            #pragma unroll
            for (int hf = 0; hf < 2; hf++) {
                const int r = row0 + tm * 16 + gr + hf * 8;
                float2 v;
                v.x = mk.x ? acc[tm][tn][hf * 2 + 0] * SCALE_F : NEG_INF;
                v.y = mk.y ? acc[tm][tn][hf * 2 + 1] * SCALE_F : NEG_INF;
                *reinterpret_cast<float2*>(sbase + (size_t)r * LQ + c) = v;
            }
    }
}

// ---------------------------------------------------------------------------
// GEMM 3: attn = P . qh^T; 2-pass (P single, qh^T split). grid (6, 16, 8)
// ---------------------------------------------------------------------------
__global__ __launch_bounds__(256, 2) void k_gemm_out(float* __restrict__ out) {
    float acc[4][4][4] = {};
    const int z = blockIdx.z;
    const size_t aoff = (size_t)z * LC * LQ + (size_t)blockIdx.y * 128 * LQ;
    const size_t boff = (size_t)z * DIM * LQ + (size_t)blockIdx.x * 128 * LQ;
    mainloop2(g_ph + aoff, LQ, g_qth + boff, g_qtl + boff, LQ, LQ / CHUNK, acc);

    const int lane = threadIdx.x & 31, wid = threadIdx.x >> 5;
    const int wm = wid & 1, wn = wid >> 1;
    const int gr = lane >> 2, gc = (lane & 3) * 2;
    const int row0 = blockIdx.y * 128 + wm * 64, col0 = blockIdx.x * 128 + wn * 32;
    float* obase = out + (size_t)z * LC * ODIM + DIM;
    #pragma unroll
    for (int tn = 0; tn < 4; tn++) {
        const int c = col0 + tn * 8 + gc;
        #pragma unroll
        for (int tm = 0; tm < 4; tm++)
            #pragma unroll
            for (int hf = 0; hf < 2; hf++) {
                const int r = row0 + tm * 16 + gr + hf * 8;
                float2 v = make_float2(acc[tm][tn][hf * 2 + 0], acc[tm][tn][hf * 2 + 1]);
                *reinterpret_cast<float2*>(obase + (size_t)r * ODIM + c) = v;
            }
    }
}

// ---------------------------------------------------------------------------
// Prep: ch -> out[0:768] copy + fp16 single
// ---------------------------------------------------------------------------
__global__ __launch_bounds__(256) void k_prep_ch(const float* __restrict__ ch,
                                                 float* __restrict__ out) {
    const size_t total4 = (size_t)BATCH * LC * (DIM / 4);
    for (size_t i = (size_t)blockIdx.x * blockDim.x + threadIdx.x; i < total4;
         i += (size_t)gridDim.x * blockDim.x) {
        float4 x = reinterpret_cast<const float4*>(ch)[i];
        size_t row = i / (DIM / 4);
        size_t d4 = i % (DIM / 4);
        reinterpret_cast<float4*>(out)[row * (ODIM / 4) + d4] = x;
        reinterpret_cast<uint2*>(g_chh)[i] =
            make_uint2(packh(__float2half_rn(x.x), __float2half_rn(x.y)),
                       packh(__float2half_rn(x.z), __float2half_rn(x.w)));
    }
}

// ---------------------------------------------------------------------------
// Prep: qh -> row-major split (qhh/qhl) + transposed split (qth/qtl)
// grid (24, 32, 8), block (32, 8)
// ---------------------------------------------------------------------------
__global__ __launch_bounds__(256) void k_prep_q(const float* __restrict__ qh) {
    __shared__ float t[32][33];
    int z = blockIdx.z;
    int d0 = blockIdx.x * 32, q0 = blockIdx.y * 32;
    const float* src = qh + (size_t)z * LQ * DIM;
    int tx = threadIdx.x, ty = threadIdx.y;
    __half* rh = g_qhh + (size_t)z * LQ * DIM;
    __half* rl = g_qhl + (size_t)z * LQ * DIM;
    #pragma unroll
    for (int i = 0; i < 4; i++) {
        int q = q0 + ty + 8 * i;
        float v = src[(size_t)q * DIM + d0 + tx];
        t[ty + 8 * i][tx] = v;
        __half h, l;
        split2h(v, h, l);
        size_t o = (size_t)q * DIM + d0 + tx;
        rh[o] = h;
        rl[o] = l;
    }
    __syncthreads();
    __half* dh = g_qth + (size_t)z * DIM * LQ;
    __half* dl = g_qtl + (size_t)z * DIM * LQ;
    #pragma unroll
    for (int i = 0; i < 4; i++) {
        float v = t[tx][ty + 8 * i];
        __half h, l;
        split2h(v, h, l);
        size_t o = (size_t)(d0 + ty + 8 * i) * LQ + q0 + tx;
        dh[o] = h;
        dl[o] = l;
    }
}

// ---------------------------------------------------------------------------
// W split
// ---------------------------------------------------------------------------
__global__ __launch_bounds__(256) void k_split_w(const float* __restrict__ src, int n4) {
    int i = blockIdx.x * blockDim.x + threadIdx.x;
    if (i >= n4) return;
    float4 x = reinterpret_cast<const float4*>(src)[i];
    __half h0, h1, h2, h3, l0, l1, l2, l3;
    split2h(x.x, h0, l0); split2h(x.y, h1, l1);
    split2h(x.z, h2, l2); split2h(x.w, h3, l3);
    reinterpret_cast<uint2*>(g_wh)[i] = make_uint2(packh(h0, h1), packh(h2, h3));
    reinterpret_cast<uint2*>(g_wl)[i] = make_uint2(packh(l0, l1), packh(l2, l3));
}

// ---------------------------------------------------------------------------
// Row softmax over Lq=1024; fp32 in, P fp16 single out. grid 16384 x 256
// ---------------------------------------------------------------------------
__global__ __launch_bounds__(256) void k_softmax() {
    const size_t rowoff = (size_t)blockIdx.x * LQ;
    const float* p = g_scores + rowoff;
    const int t = threadIdx.x;
    float4 v = reinterpret_cast<const float4*>(p)[t];

    __shared__ float red[8];
    float m = fmaxf(fmaxf(v.x, v.y), fmaxf(v.z, v.w));
    #pragma unroll
    for (int o = 16; o; o >>= 1) m = fmaxf(m, __shfl_xor_sync(0xffffffffu, m, o));
    if ((t & 31) == 0) red[t >> 5] = m;
    __syncthreads();
    m = red[0];
    #pragma unroll
    for (int w = 1; w < 8; w++) m = fmaxf(m, red[w]);
    __syncthreads();

    v.x = __expf(v.x - m); v.y = __expf(v.y - m);
    v.z = __expf(v.z - m); v.w = __expf(v.w - m);
    float s = v.x + v.y + v.z + v.w;
    #pragma unroll
    for (int o = 16; o; o >>= 1) s += __shfl_xor_sync(0xffffffffu, s, o);
    if ((t & 31) == 0) red[t >> 5] = s;
    __syncthreads();
    s = red[0];
    #pragma unroll
    for (int w = 1; w < 8; w++) s += red[w];

    float inv = 1.0f / s;
    v.x *= inv; v.y *= inv; v.z *= inv; v.w *= inv;

    reinterpret_cast<uint2*>(g_ph + rowoff)[t] =
        make_uint2(packh(__float2half_rn(v.x), __float2half_rn(v.y)),
                   packh(__float2half_rn(v.z), __float2half_rn(v.w)));
}

// ---------------------------------------------------------------------------
extern "C" void kernel_launch(void* const* d_in, const int* in_sizes, int n_in,
                              void* d_out, int out_size) {
    const float* ch    = (const float*)d_in[0];
    const float* qh    = (const float*)d_in[2];
    const int*   qmask = (const int*)d_in[3];
    const float* W     = (const float*)d_in[4];
    const float* bias  = (const float*)d_in[5];
    float*       out   = (float*)d_out;

    cudaFuncSetAttribute(k_gemm_query, cudaFuncAttributeMaxDynamicSharedMemorySize, SMEM_DYN);
    cudaFuncSetAttribute(k_gemm_scores, cudaFuncAttributeMaxDynamicSharedMemorySize, SMEM_DYN);
    cudaFuncSetAttribute(k_gemm_out, cudaFuncAttributeMaxDynamicSharedMemorySize, SMEM_DYN);

    int n4_w = DIM * DIM / 4;
    k_prep_q<<<dim3(DIM / 32, LQ / 32, BATCH), dim3(32, 8)>>>(qh);
    k_split_w<<<(n4_w + 255) / 256, 256>>>(W, n4_w);
    k_gemm_query<<<dim3(DIM / 128, BATCH * LQ / 128), 256, SMEM_DYN>>>(bias);
    k_prep_ch<<<1184, 256>>>(ch, out);
    k_gemm_scores<<<dim3(LQ / 128, LC / 128, BATCH), 256, SMEM_DYN>>>(qmask);
    k_softmax<<<BATCH * LC, 256>>>();
    k_gemm_out<<<dim3(DIM / 128, LC / 128, BATCH), 256, SMEM_DYN>>>(out);
}

// round 11
// speedup vs baseline: 1.7082x; 1.2747x over previous
#include <cuda_runtime.h>
#include <cuda_fp16.h>
#include <cstdint>

#define BATCH 8
#define LC    2048
#define LQ    1024
#define DIM   768
#define ODIM  1536

#define NEG_INF (-1e30f)
#define SCALE_F 0.03608439182435161f  // 1/sqrt(768)

// ---------------------------------------------------------------------------
// Scratch (__device__ globals; allocation-free rule). fp16 operands.
// ---------------------------------------------------------------------------
__device__ __align__(16) __half g_chh[(size_t)BATCH * LC * DIM];   // ch single
__device__ __align__(16) __half g_qhh[(size_t)BATCH * LQ * DIM];   // qh single (row-major)
__device__ __align__(16) __half g_qth[(size_t)BATCH * DIM * LQ];   // qh^T single
__device__ __align__(16) __half g_wh[DIM * DIM];
__device__ __align__(16) __half g_wl[DIM * DIM];
__device__ __align__(16) __half g_qryh[(size_t)BATCH * LQ * DIM];
__device__ __align__(16) __half g_qryl[(size_t)BATCH * LQ * DIM];
__device__ __align__(16) float  g_scores[(size_t)BATCH * LC * LQ];
__device__ __align__(16) __half g_ph[(size_t)BATCH * LC * LQ];     // P single

// ---------------------------------------------------------------------------
// helpers
// ---------------------------------------------------------------------------
static __device__ __forceinline__ uint32_t smem_u32(const void* p) {
    uint32_t r;
    asm("{ .reg .u64 t; cvta.to.shared.u64 t, %1; cvt.u32.u64 %0, t; }"
        : "=r"(r) : "l"(p));
    return r;
}
static __device__ __forceinline__ void cp16(uint32_t dst, const void* src) {
    asm volatile("cp.async.cg.shared.global [%0], [%1], 16;" :: "r"(dst), "l"(src));
}
static __device__ __forceinline__ void split2h(float x, __half& h, __half& l) {
    h = __float2half_rn(x);
    l = __float2half_rn(x - __half2float(h));
}
static __device__ __forceinline__ uint32_t packh(__half a, __half b) {
    __half2 t = __halves2half2(a, b);
    return *reinterpret_cast<uint32_t*>(&t);
}

#define LDSM_X4(r0, r1, r2, r3, addr) \
    asm volatile("ldmatrix.sync.aligned.m8n8.x4.shared.b16 {%0,%1,%2,%3}, [%4];" \
                 : "=r"(r0), "=r"(r1), "=r"(r2), "=r"(r3) : "r"(addr))

#define MMA16816(d, a, b) \
    asm volatile("mma.sync.aligned.m16n8k16.row.col.f32.f16.f16.f32 " \
                 "{%0,%1,%2,%3}, {%4,%5,%6,%7}, {%8,%9}, {%0,%1,%2,%3};" \
                 : "+f"((d)[0]), "+f"((d)[1]), "+f"((d)[2]), "+f"((d)[3]) \
                 : "r"((a)[0]), "r"((a)[1]), "r"((a)[2]), "r"((a)[3]), \
                   "r"((b)[0]), "r"((b)[1]))

// ---------------------------------------------------------------------------
// Tiles (k-chunk = 32 fp16):
//   split tile : 128 rows x 128B (32 hi | 32 lo), swz128
//   single tile: 128 rows x  64B (32 fp16),       swz64
// ---------------------------------------------------------------------------
#define CHUNK 32
#define STILE_B 16384
#define NTILE_B 8192

static __device__ __forceinline__ uint32_t swz128(uint32_t row, uint32_t kb) {
    return (row * 128 + kb) ^ ((row & 7) << 4);
}
static __device__ __forceinline__ uint32_t swz64(uint32_t row, uint32_t kb) {
    return row * 64 + (kb ^ (((row >> 1) & 3) << 4));
}

// GEMM1/2 stage: A single (8KB) + B split (16KB) = 24KB, 4 stages = 96KB
#define STAGE2_B (NTILE_B + STILE_B)
// GEMM3 stage: A single + B single = 16KB, 4 stages = 64KB
#define STAGE3_B (2 * NTILE_B)
#define SMEM_DYN2 98304
#define SMEM_DYN3 65536

// ---- loaders ----
static __device__ __forceinline__ void load_split(uint32_t tb,
    const __half* __restrict__ H, const __half* __restrict__ L, int ld, int k0, int tid) {
    #pragma unroll
    for (int i = 0; i < 4; i++) {
        int idx = tid + i * 256;
        int row = idx >> 3, seg = idx & 7;
        const __half* s = (seg < 4) ? (H + (size_t)row * ld + k0 + seg * 8)
                                    : (L + (size_t)row * ld + k0 + (seg - 4) * 8);
        cp16(tb + swz128(row, seg * 16), (const void*)s);
    }
}
static __device__ __forceinline__ void load_single(uint32_t tb,
    const __half* __restrict__ H, int ld, int k0, int tid) {
    #pragma unroll
    for (int i = 0; i < 2; i++) {
        int idx = tid + i * 256;
        int row = idx >> 2, seg = idx & 3;
        cp16(tb + swz64(row, seg * 16), (const void*)(H + (size_t)row * ld + k0 + seg * 8));
    }
}

// ---- compute: 2-pass (A single + B split), warp tile 64x32 ----
static __device__ __forceinline__ void compute2(uint32_t sb, int wm, int wn, int lane,
                                                float acc[4][4][4]) {
    const uint32_t tA = sb, tB = sb + NTILE_B;
    #pragma unroll
    for (int ks = 0; ks < 2; ks++) {
        const uint32_t akb = ks * 32 + ((lane >> 4) << 4);
        const uint32_t arow = wm * 64 + (lane & 15);
        uint32_t a[4][4];
        #pragma unroll
        for (int tm = 0; tm < 4; tm++)
            LDSM_X4(a[tm][0], a[tm][1], a[tm][2], a[tm][3], tA + swz64(arow + tm * 16, akb));
        const uint32_t brow = wn * 32 + (lane & 7) + ((lane >> 4) << 3);
        const uint32_t bkb = ks * 32 + (((lane >> 3) & 1) << 4);
        uint32_t b[4][2];
        #pragma unroll
        for (int tp = 0; tp < 2; tp++) {
            uint32_t t0, t1, t2, t3;
            LDSM_X4(t0, t1, t2, t3, tB + swz128(brow + tp * 16, bkb));
            b[tp * 2][0] = t0; b[tp * 2][1] = t1;
            b[tp * 2 + 1][0] = t2; b[tp * 2 + 1][1] = t3;
        }
        #pragma unroll
        for (int tm = 0; tm < 4; tm++)
            #pragma unroll
            for (int tn = 0; tn < 4; tn++)
                MMA16816(acc[tm][tn], a[tm], b[tn]);
        #pragma unroll
        for (int tp = 0; tp < 2; tp++) {
            uint32_t t0, t1, t2, t3;
            LDSM_X4(t0, t1, t2, t3, tB + swz128(brow + tp * 16, 64 + bkb));
            b[tp * 2][0] = t0; b[tp * 2][1] = t1;
            b[tp * 2 + 1][0] = t2; b[tp * 2 + 1][1] = t3;
        }
        #pragma unroll
        for (int tm = 0; tm < 4; tm++)
            #pragma unroll
            for (int tn = 0; tn < 4; tn++)
                MMA16816(acc[tm][tn], a[tm], b[tn]);
    }
}

// ---- compute: 1-pass (A single + B single) ----
static __device__ __forceinline__ void compute1(uint32_t sb, int wm, int wn, int lane,
                                                float acc[4][4][4]) {
    const uint32_t tA = sb, tB = sb + NTILE_B;
    #pragma unroll
    for (int ks = 0; ks < 2; ks++) {
        const uint32_t akb = ks * 32 + ((lane >> 4) << 4);
        const uint32_t arow = wm * 64 + (lane & 15);
        uint32_t a[4][4];
        #pragma unroll
        for (int tm = 0; tm < 4; tm++)
            LDSM_X4(a[tm][0], a[tm][1], a[tm][2], a[tm][3], tA + swz64(arow + tm * 16, akb));
        const uint32_t brow = wn * 32 + (lane & 7) + ((lane >> 4) << 3);
        const uint32_t bkb = ks * 32 + (((lane >> 3) & 1) << 4);
        uint32_t b[4][2];
        #pragma unroll
        for (int tp = 0; tp < 2; tp++) {
            uint32_t t0, t1, t2, t3;
            LDSM_X4(t0, t1, t2, t3, tB + swz64(brow + tp * 16, bkb));
            b[tp * 2][0] = t0; b[tp * 2][1] = t1;
            b[tp * 2 + 1][0] = t2; b[tp * 2 + 1][1] = t3;
        }
        #pragma unroll
        for (int tm = 0; tm < 4; tm++)
            #pragma unroll
            for (int tn = 0; tn < 4; tn++)
                MMA16816(acc[tm][tn], a[tm], b[tn]);
    }
}

// ---- mainloops: single __syncthreads per iteration ----
static __device__ __forceinline__ void mainloop2(
    const __half* A, int ldA,
    const __half* Bh, const __half* Bl, int ldB, int nk, float acc[4][4][4]) {
    extern __shared__ char smem[];
    const uint32_t sb = smem_u32(smem);
    const int tid = threadIdx.x, lane = tid & 31, wid = tid >> 5;
    const int wm = wid & 1, wn = wid >> 1;

    #pragma unroll
    for (int p = 0; p < 3; p++) {
        uint32_t st = sb + p * STAGE2_B;
        load_single(st, A, ldA, p * CHUNK, tid);
        load_split(st + NTILE_B, Bh, Bl, ldB, p * CHUNK, tid);
        asm volatile("cp.async.commit_group;" ::: "memory");
    }
    for (int k = 0; k < nk; k++) {
        if (k + 2 < nk)      asm volatile("cp.async.wait_group 2;" ::: "memory");
        else if (k + 1 < nk) asm volatile("cp.async.wait_group 1;" ::: "memory");
        else                 asm volatile("cp.async.wait_group 0;" ::: "memory");
        __syncthreads();
        if (k + 3 < nk) {
            uint32_t st = sb + ((k + 3) & 3) * STAGE2_B;
            load_single(st, A, ldA, (k + 3) * CHUNK, tid);
            load_split(st + NTILE_B, Bh, Bl, ldB, (k + 3) * CHUNK, tid);
            asm volatile("cp.async.commit_group;" ::: "memory");
        }
        compute2(sb + (k & 3) * STAGE2_B, wm, wn, lane, acc);
    }
}

static __device__ __forceinline__ void mainloop1(
    const __half* A, int ldA, const __half* B, int ldB, int nk, float acc[4][4][4]) {
    extern __shared__ char smem[];
    const uint32_t sb = smem_u32(smem);
    const int tid = threadIdx.x, lane = tid & 31, wid = tid >> 5;
    const int wm = wid & 1, wn = wid >> 1;

    #pragma unroll
    for (int p = 0; p < 3; p++) {
        uint32_t st = sb + p * STAGE3_B;
        load_single(st, A, ldA, p * CHUNK, tid);
        load_single(st + NTILE_B, B, ldB, p * CHUNK, tid);
        asm volatile("cp.async.commit_group;" ::: "memory");
    }
    for (int k = 0; k < nk; k++) {
        if (k + 2 < nk)      asm volatile("cp.async.wait_group 2;" ::: "memory");
        else if (k + 1 < nk) asm volatile("cp.async.wait_group 1;" ::: "memory");
        else                 asm volatile("cp.async.wait_group 0;" ::: "memory");
        __syncthreads();
        if (k + 3 < nk) {
            uint32_t st = sb + ((k + 3) & 3) * STAGE3_B;
            load_single(st, A, ldA, (k + 3) * CHUNK, tid);
            load_single(st + NTILE_B, B, ldB, (k + 3) * CHUNK, tid);
            asm volatile("cp.async.commit_group;" ::: "memory");
        }
        compute1(sb + (k & 3) * STAGE3_B, wm, wn, lane, acc);
    }
}

// ---------------------------------------------------------------------------
// GEMM 1: query[m,e] = qh[m,:] . W[e,:] + b[e]; 2-pass (qh single, W split).
// fp16 hi/lo out. grid (6, 64)
// ---------------------------------------------------------------------------
__global__ __launch_bounds__(256, 2) void k_gemm_query(const float* __restrict__ bias) {
    float acc[4][4][4] = {};
    const size_t aoff = (size_t)blockIdx.y * 128 * DIM;
    const size_t boff = (size_t)blockIdx.x * 128 * DIM;
    mainloop2(g_qhh + aoff, DIM, g_wh + boff, g_wl + boff, DIM, DIM / CHUNK, acc);

    const int lane = threadIdx.x & 31, wid = threadIdx.x >> 5;
    const int wm = wid & 1, wn = wid >> 1;
    const int gr = lane >> 2, gc = (lane & 3) * 2;
    const int row0 = blockIdx.y * 128 + wm * 64, col0 = blockIdx.x * 128 + wn * 32;
    #pragma unroll
    for (int tn = 0; tn < 4; tn++) {
        const int c = col0 + tn * 8 + gc;
        const float2 bb = *reinterpret_cast<const float2*>(bias + c);
        #pragma unroll
        for (int tm = 0; tm < 4; tm++)
            #pragma unroll
            for (int hf = 0; hf < 2; hf++) {
                const int r = row0 + tm * 16 + gr + hf * 8;
                float v0 = acc[tm][tn][hf * 2 + 0] + bb.x;
                float v1 = acc[tm][tn][hf * 2 + 1] + bb.y;
                __half h0, l0, h1, l1;
                split2h(v0, h0, l0);
                split2h(v1, h1, l1);
                const size_t o = (size_t)r * DIM + c;
                *reinterpret_cast<uint32_t*>(&g_qryh[o]) = packh(h0, h1);
                *reinterpret_cast<uint32_t*>(&g_qryl[o]) = packh(l0, l1);
            }
    }
}

// ---------------------------------------------------------------------------
// GEMM 2: scores = SCALE * ch . query^T; mask -> -1e30; 2-pass. grid (8, 16, 8)
// ---------------------------------------------------------------------------
__global__ __launch_bounds__(256, 2) void k_gemm_scores(const int* __restrict__ qmask) {
    float acc[4][4][4] = {};
    const int z = blockIdx.z;
    const size_t aoff = (size_t)z * LC * DIM + (size_t)blockIdx.y * 128 * DIM;
    const size_t boff = (size_t)z * LQ * DIM + (size_t)blockIdx.x * 128 * DIM;
    mainloop2(g_chh + aoff, DIM, g_qryh + boff, g_qryl + boff, DIM, DIM / CHUNK, acc);

    const int lane = threadIdx.x & 31, wid = threadIdx.x >> 5;
    const int wm = wid & 1, wn = wid >> 1;
    const int gr = lane >> 2, gc = (lane & 3) * 2;
    const int row0 = blockIdx.y * 128 + wm * 64, col0 = blockIdx.x * 128 + wn * 32;
    float* sbase = g_scores + (size_t)z * LC * LQ;
    const int* mrow = qmask + (size_t)z * LQ;
    #pragma unroll
    for (int tn = 0; tn < 4; tn++) {
        const int c = col0 + tn * 8 + gc;
        const int2 mk = *reinterpret_cast<const int2*>(mrow + c);
        #pragma unroll
        for (int tm = 0; tm < 4; tm++)
            #pragma unroll
            for (int hf = 0; hf < 2; hf++) {
                const int r = row0 + tm * 16 + gr + hf * 8;
                float2 v;
                v.x = mk.x ? acc[tm][tn][hf * 2 + 0] * SCALE_F : NEG_INF;
                v.y = mk.y ? acc[tm][tn][hf * 2 + 1] * SCALE_F : NEG_INF;
                *reinterpret_cast<float2*>(sbase + (size_t)r * LQ + c) = v;
            }
    }
}

// ---------------------------------------------------------------------------
// GEMM 3: attn = P . qh^T; 1-pass (both single). grid (6, 16, 8)
// ---------------------------------------------------------------------------
__global__ __launch_bounds__(256, 2) void k_gemm_out(float* __restrict__ out) {
    float acc[4][4][4] = {};
    const int z = blockIdx.z;
    const size_t aoff = (size_t)z * LC * LQ + (size_t)blockIdx.y * 128 * LQ;
    const size_t boff = (size_t)z * DIM * LQ + (size_t)blockIdx.x * 128 * LQ;
    mainloop1(g_ph + aoff, LQ, g_qth + boff, LQ, LQ / CHUNK, acc);

    const int lane = threadIdx.x & 31, wid = threadIdx.x >> 5;
    const int wm = wid & 1, wn = wid >> 1;
    const int gr = lane >> 2, gc = (lane & 3) * 2;
    const int row0 = blockIdx.y * 128 + wm * 64, col0 = blockIdx.x * 128 + wn * 32;
    float* obase = out + (size_t)z * LC * ODIM + DIM;
    #pragma unroll
    for (int tn = 0; tn < 4; tn++) {
        const int c = col0 + tn * 8 + gc;
        #pragma unroll
        for (int tm = 0; tm < 4; tm++)
            #pragma unroll
            for (int hf = 0; hf < 2; hf++) {
                const int r = row0 + tm * 16 + gr + hf * 8;
                float2 v = make_float2(acc[tm][tn][hf * 2 + 0], acc[tm][tn][hf * 2 + 1]);
                *reinterpret_cast<float2*>(obase + (size_t)r * ODIM + c) = v;
            }
    }
}

// ---------------------------------------------------------------------------
// Prep: ch -> out[0:768] copy + fp16 single
// ---------------------------------------------------------------------------
__global__ __launch_bounds__(256) void k_prep_ch(const float* __restrict__ ch,
                                                 float* __restrict__ out) {
    const size_t total4 = (size_t)BATCH * LC * (DIM / 4);
    for (size_t i = (size_t)blockIdx.x * blockDim.x + threadIdx.x; i < total4;
         i += (size_t)gridDim.x * blockDim.x) {
        float4 x = reinterpret_cast<const float4*>(ch)[i];
        size_t row = i / (DIM / 4);
        size_t d4 = i % (DIM / 4);
        reinterpret_cast<float4*>(out)[row * (ODIM / 4) + d4] = x;
        reinterpret_cast<uint2*>(g_chh)[i] =
            make_uint2(packh(__float2half_rn(x.x), __float2half_rn(x.y)),
                       packh(__float2half_rn(x.z), __float2half_rn(x.w)));
    }
}

// ---------------------------------------------------------------------------
// Prep: qh -> row-major single (qhh) + transposed single (qth)
// grid (24, 32, 8), block (32, 8)
// ---------------------------------------------------------------------------
__global__ __launch_bounds__(256) void k_prep_q(const float* __restrict__ qh) {
    __shared__ float t[32][33];
    int z = blockIdx.z;
    int d0 = blockIdx.x * 32, q0 = blockIdx.y * 32;
    const float* src = qh + (size_t)z * LQ * DIM;
    int tx = threadIdx.x, ty = threadIdx.y;
    __half* rh = g_qhh + (size_t)z * LQ * DIM;
    #pragma unroll
    for (int i = 0; i < 4; i++) {
        int q = q0 + ty + 8 * i;
        float v = src[(size_t)q * DIM + d0 + tx];
        t[ty + 8 * i][tx] = v;
        rh[(size_t)q * DIM + d0 + tx] = __float2half_rn(v);
    }
    __syncthreads();
    __half* dh = g_qth + (size_t)z * DIM * LQ;
    #pragma unroll
    for (int i = 0; i < 4; i++) {
        float v = t[tx][ty + 8 * i];
        dh[(size_t)(d0 + ty + 8 * i) * LQ + q0 + tx] = __float2half_rn(v);
    }
}

// ---------------------------------------------------------------------------
// W split
// ---------------------------------------------------------------------------
__global__ __launch_bounds__(256) void k_split_w(const float* __restrict__ src, int n4) {
    int i = blockIdx.x * blockDim.x + threadIdx.x;
    if (i >= n4) return;
    float4 x = reinterpret_cast<const float4*>(src)[i];
    __half h0, h1, h2, h3, l0, l1, l2, l3;
    split2h(x.x, h0, l0); split2h(x.y, h1, l1);
    split2h(x.z, h2, l2); split2h(x.w, h3, l3);
    reinterpret_cast<uint2*>(g_wh)[i] = make_uint2(packh(h0, h1), packh(h2, h3));
    reinterpret_cast<uint2*>(g_wl)[i] = make_uint2(packh(l0, l1), packh(l2, l3));
}

// ---------------------------------------------------------------------------
// Row softmax over Lq=1024; fp32 in, P fp16 single out. grid 16384 x 256
// ---------------------------------------------------------------------------
__global__ __launch_bounds__(256) void k_softmax() {
    const size_t rowoff = (size_t)blockIdx.x * LQ;
    const float* p = g_scores + rowoff;
    const int t = threadIdx.x;
    float4 v = reinterpret_cast<const float4*>(p)[t];

    __shared__ float red[8];
    float m = fmaxf(fmaxf(v.x, v.y), fmaxf(v.z, v.w));
    #pragma unroll
    for (int o = 16; o; o >>= 1) m = fmaxf(m, __shfl_xor_sync(0xffffffffu, m, o));
    if ((t & 31) == 0) red[t >> 5] = m;
    __syncthreads();
    m = red[0];
    #pragma unroll
    for (int w = 1; w < 8; w++) m = fmaxf(m, red[w]);
    __syncthreads();

    v.x = __expf(v.x - m); v.y = __expf(v.y - m);
    v.z = __expf(v.z - m); v.w = __expf(v.w - m);
    float s = v.x + v.y + v.z + v.w;
    #pragma unroll
    for (int o = 16; o; o >>= 1) s += __shfl_xor_sync(0xffffffffu, s, o);
    if ((t & 31) == 0) red[t >> 5] = s;
    __syncthreads();
    s = red[0];
    #pragma unroll
    for (int w = 1; w < 8; w++) s += red[w];

    float inv = 1.0f / s;
    v.x *= inv; v.y *= inv; v.z *= inv; v.w *= inv;

    reinterpret_cast<uint2*>(g_ph + rowoff)[t] =
        make_uint2(packh(__float2half_rn(v.x), __float2half_rn(v.y)),
                   packh(__float2half_rn(v.z), __float2half_rn(v.w)));
}

// ---------------------------------------------------------------------------
extern "C" void kernel_launch(void* const* d_in, const int* in_sizes, int n_in,
                              void* d_out, int out_size) {
    const float* ch    = (const float*)d_in[0];
    const float* qh    = (const float*)d_in[2];
    const int*   qmask = (const int*)d_in[3];
    const float* W     = (const float*)d_in[4];
    const float* bias  = (const float*)d_in[5];
    float*       out   = (float*)d_out;

    cudaFuncSetAttribute(k_gemm_query, cudaFuncAttributeMaxDynamicSharedMemorySize, SMEM_DYN2);
    cudaFuncSetAttribute(k_gemm_scores, cudaFuncAttributeMaxDynamicSharedMemorySize, SMEM_DYN2);
    cudaFuncSetAttribute(k_gemm_out, cudaFuncAttributeMaxDynamicSharedMemorySize, SMEM_DYN3);

    int n4_w = DIM * DIM / 4;
    k_prep_q<<<dim3(DIM / 32, LQ / 32, BATCH), dim3(32, 8)>>>(qh);
    k_split_w<<<(n4_w + 255) / 256, 256>>>(W, n4_w);
    k_gemm_query<<<dim3(DIM / 128, BATCH * LQ / 128), 256, SMEM_DYN2>>>(bias);
    k_prep_ch<<<1184, 256>>>(ch, out);
    k_gemm_scores<<<dim3(LQ / 128, LC / 128, BATCH), 256, SMEM_DYN2>>>(qmask);
    k_softmax<<<BATCH * LC, 256>>>();
    k_gemm_out<<<dim3(DIM / 128, LC / 128, BATCH), 256, SMEM_DYN3>>>(out);
}

// round 13
// speedup vs baseline: 2.0695x; 1.2115x over previous
#include <cuda_runtime.h>
#include <cuda_fp16.h>
#include <cstdint>

#define BATCH 8
#define LC    2048
#define LQ    1024
#define DIM   768
#define ODIM  1536

#define NEG_INF (-1e30f)
#define SCALE_F 0.03608439182435161f  // 1/sqrt(768)

// ---------------------------------------------------------------------------
// Scratch (__device__ globals; allocation-free rule). fp16 operands.
// ---------------------------------------------------------------------------
__device__ __align__(16) __half g_chh[(size_t)BATCH * LC * DIM];   // ch single
__device__ __align__(16) __half g_qhh[(size_t)BATCH * LQ * DIM];   // qh single (row-major)
__device__ __align__(16) __half g_qth[(size_t)BATCH * DIM * LQ];   // qh^T single
__device__ __align__(16) __half g_wh[DIM * DIM];
__device__ __align__(16) __half g_wl[DIM * DIM];
__device__ __align__(16) __half g_qryh[(size_t)BATCH * LQ * DIM];  // query single
__device__ __align__(16) float  g_scores[(size_t)BATCH * LC * LQ];
__device__ __align__(16) __half g_ph[(size_t)BATCH * LC * LQ];     // P single

// ---------------------------------------------------------------------------
// helpers
// ---------------------------------------------------------------------------
static __device__ __forceinline__ uint32_t smem_u32(const void* p) {
    uint32_t r;
    asm("{ .reg .u64 t; cvta.to.shared.u64 t, %1; cvt.u32.u64 %0, t; }"
        : "=r"(r) : "l"(p));
    return r;
}
static __device__ __forceinline__ void cp16(uint32_t dst, const void* src) {
    asm volatile("cp.async.cg.shared.global [%0], [%1], 16;" :: "r"(dst), "l"(src));
}
static __device__ __forceinline__ void split2h(float x, __half& h, __half& l) {
    h = __float2half_rn(x);
    l = __float2half_rn(x - __half2float(h));
}
static __device__ __forceinline__ uint32_t packh(__half a, __half b) {
    __half2 t = __halves2half2(a, b);
    return *reinterpret_cast<uint32_t*>(&t);
}

#define LDSM_X4(r0, r1, r2, r3, addr) \
    asm volatile("ldmatrix.sync.aligned.m8n8.x4.shared.b16 {%0,%1,%2,%3}, [%4];" \
                 : "=r"(r0), "=r"(r1), "=r"(r2), "=r"(r3) : "r"(addr))

#define MMA16816(d, a, b) \
    asm volatile("mma.sync.aligned.m16n8k16.row.col.f32.f16.f16.f32 " \
                 "{%0,%1,%2,%3}, {%4,%5,%6,%7}, {%8,%9}, {%0,%1,%2,%3};" \
                 : "+f"((d)[0]), "+f"((d)[1]), "+f"((d)[2]), "+f"((d)[3]) \
                 : "r"((a)[0]), "r"((a)[1]), "r"((a)[2]), "r"((a)[3]), \
                   "r"((b)[0]), "r"((b)[1]))

// ---------------------------------------------------------------------------
// Tiles (k-chunk = 32 fp16):
//   split tile : 128 rows x 128B (32 hi | 32 lo), swz128
//   single tile: 128 rows x  64B (32 fp16),       swz64
// ---------------------------------------------------------------------------
#define CHUNK 32
#define STILE_B 16384
#define NTILE_B 8192

static __device__ __forceinline__ uint32_t swz128(uint32_t row, uint32_t kb) {
    return (row * 128 + kb) ^ ((row & 7) << 4);
}
static __device__ __forceinline__ uint32_t swz64(uint32_t row, uint32_t kb) {
    return row * 64 + (kb ^ (((row >> 1) & 3) << 4));
}

// GEMM1 stage: A single (8KB) + B split (16KB) = 24KB, 4 stages = 96KB
#define STAGE2_B (NTILE_B + STILE_B)
// GEMM2/3 stage: A single + B single = 16KB, 4 stages = 64KB
#define STAGE3_B (2 * NTILE_B)
#define SMEM_DYN2 98304
#define SMEM_DYN3 65536

// ---- loaders ----
static __device__ __forceinline__ void load_split(uint32_t tb,
    const __half* __restrict__ H, const __half* __restrict__ L, int ld, int k0, int tid) {
    #pragma unroll
    for (int i = 0; i < 4; i++) {
        int idx = tid + i * 256;
        int row = idx >> 3, seg = idx & 7;
        const __half* s = (seg < 4) ? (H + (size_t)row * ld + k0 + seg * 8)
                                    : (L + (size_t)row * ld + k0 + (seg - 4) * 8);
        cp16(tb + swz128(row, seg * 16), (const void*)s);
    }
}
static __device__ __forceinline__ void load_single(uint32_t tb,
    const __half* __restrict__ H, int ld, int k0, int tid) {
    #pragma unroll
    for (int i = 0; i < 2; i++) {
        int idx = tid + i * 256;
        int row = idx >> 2, seg = idx & 3;
        cp16(tb + swz64(row, seg * 16), (const void*)(H + (size_t)row * ld + k0 + seg * 8));
    }
}

// ---- compute: 2-pass (A single + B split), warp tile 64x32 ----
static __device__ __forceinline__ void compute2(uint32_t sb, int wm, int wn, int lane,
                                                float acc[4][4][4]) {
    const uint32_t tA = sb, tB = sb + NTILE_B;
    #pragma unroll
    for (int ks = 0; ks < 2; ks++) {
        const uint32_t akb = ks * 32 + ((lane >> 4) << 4);
        const uint32_t arow = wm * 64 + (lane & 15);
        uint32_t a[4][4];
        #pragma unroll
        for (int tm = 0; tm < 4; tm++)
            LDSM_X4(a[tm][0], a[tm][1], a[tm][2], a[tm][3], tA + swz64(arow + tm * 16, akb));
        const uint32_t brow = wn * 32 + (lane & 7) + ((lane >> 4) << 3);
        const uint32_t bkb = ks * 32 + (((lane >> 3) & 1) << 4);
        uint32_t b[4][2];
        #pragma unroll
        for (int tp = 0; tp < 2; tp++) {
            uint32_t t0, t1, t2, t3;
            LDSM_X4(t0, t1, t2, t3, tB + swz128(brow + tp * 16, bkb));
            b[tp * 2][0] = t0; b[tp * 2][1] = t1;
            b[tp * 2 + 1][0] = t2; b[tp * 2 + 1][1] = t3;
        }
        #pragma unroll
        for (int tm = 0; tm < 4; tm++)
            #pragma unroll
            for (int tn = 0; tn < 4; tn++)
                MMA16816(acc[tm][tn], a[tm], b[tn]);
        #pragma unroll
        for (int tp = 0; tp < 2; tp++) {
            uint32_t t0, t1, t2, t3;
            LDSM_X4(t0, t1, t2, t3, tB + swz128(brow + tp * 16, 64 + bkb));
            b[tp * 2][0] = t0; b[tp * 2][1] = t1;
            b[tp * 2 + 1][0] = t2; b[tp * 2 + 1][1] = t3;
        }
        #pragma unroll
        for (int tm = 0; tm < 4; tm++)
            #pragma unroll
            for (int tn = 0; tn < 4; tn++)
                MMA16816(acc[tm][tn], a[tm], b[tn]);
    }
}

// ---- compute: 1-pass (A single + B single) ----
static __device__ __forceinline__ void compute1(uint32_t sb, int wm, int wn, int lane,
                                                float acc[4][4][4]) {
    const uint32_t tA = sb, tB = sb + NTILE_B;
    #pragma unroll
    for (int ks = 0; ks < 2; ks++) {
        const uint32_t akb = ks * 32 + ((lane >> 4) << 4);
        const uint32_t arow = wm * 64 + (lane & 15);
        uint32_t a[4][4];
        #pragma unroll
        for (int tm = 0; tm < 4; tm++)
            LDSM_X4(a[tm][0], a[tm][1], a[tm][2], a[tm][3], tA + swz64(arow + tm * 16, akb));
        const uint32_t brow = wn * 32 + (lane & 7) + ((lane >> 4) << 3);
        const uint32_t bkb = ks * 32 + (((lane >> 3) & 1) << 4);
        uint32_t b[4][2];
        #pragma unroll
        for (int tp = 0; tp < 2; tp++) {
            uint32_t t0, t1, t2, t3;
            LDSM_X4(t0, t1, t2, t3, tB + swz64(brow + tp * 16, bkb));
            b[tp * 2][0] = t0; b[tp * 2][1] = t1;
            b[tp * 2 + 1][0] = t2; b[tp * 2 + 1][1] = t3;
        }
        #pragma unroll
        for (int tm = 0; tm < 4; tm++)
            #pragma unroll
            for (int tn = 0; tn < 4; tn++)
                MMA16816(acc[tm][tn], a[tm], b[tn]);
    }
}

// ---- mainloops: single __syncthreads per iteration ----
static __device__ __forceinline__ void mainloop2(
    const __half* A, int ldA,
    const __half* Bh, const __half* Bl, int ldB, int nk, float acc[4][4][4]) {
    extern __shared__ char smem[];
    const uint32_t sb = smem_u32(smem);
    const int tid = threadIdx.x, lane = tid & 31, wid = tid >> 5;
    const int wm = wid & 1, wn = wid >> 1;

    #pragma unroll
    for (int p = 0; p < 3; p++) {
        uint32_t st = sb + p * STAGE2_B;
        load_single(st, A, ldA, p * CHUNK, tid);
        load_split(st + NTILE_B, Bh, Bl, ldB, p * CHUNK, tid);
        asm volatile("cp.async.commit_group;" ::: "memory");
    }
    for (int k = 0; k < nk; k++) {
        if (k + 2 < nk)      asm volatile("cp.async.wait_group 2;" ::: "memory");
        else if (k + 1 < nk) asm volatile("cp.async.wait_group 1;" ::: "memory");
        else                 asm volatile("cp.async.wait_group 0;" ::: "memory");
        __syncthreads();
        if (k + 3 < nk) {
            uint32_t st = sb + ((k + 3) & 3) * STAGE2_B;
            load_single(st, A, ldA, (k + 3) * CHUNK, tid);
            load_split(st + NTILE_B, Bh, Bl, ldB, (k + 3) * CHUNK, tid);
            asm volatile("cp.async.commit_group;" ::: "memory");
        }
        compute2(sb + (k & 3) * STAGE2_B, wm, wn, lane, acc);
    }
}

static __device__ __forceinline__ void mainloop1(
    const __half* A, int ldA, const __half* B, int ldB, int nk, float acc[4][4][4]) {
    extern __shared__ char smem[];
    const uint32_t sb = smem_u32(smem);
    const int tid = threadIdx.x, lane = tid & 31, wid = tid >> 5;
    const int wm = wid & 1, wn = wid >> 1;

    #pragma unroll
    for (int p = 0; p < 3; p++) {
        uint32_t st = sb + p * STAGE3_B;
        load_single(st, A, ldA, p * CHUNK, tid);
        load_single(st + NTILE_B, B, ldB, p * CHUNK, tid);
        asm volatile("cp.async.commit_group;" ::: "memory");
    }
    for (int k = 0; k < nk; k++) {
        if (k + 2 < nk)      asm volatile("cp.async.wait_group 2;" ::: "memory");
        else if (k + 1 < nk) asm volatile("cp.async.wait_group 1;" ::: "memory");
        else                 asm volatile("cp.async.wait_group 0;" ::: "memory");
        __syncthreads();
        if (k + 3 < nk) {
            uint32_t st = sb + ((k + 3) & 3) * STAGE3_B;
            load_single(st, A, ldA, (k + 3) * CHUNK, tid);
            load_single(st + NTILE_B, B, ldB, (k + 3) * CHUNK, tid);
            asm volatile("cp.async.commit_group;" ::: "memory");
        }
        compute1(sb + (k & 3) * STAGE3_B, wm, wn, lane, acc);
    }
}

// ---------------------------------------------------------------------------
// GEMM 1: query[m,e] = qh[m,:] . W[e,:] + b[e]; 2-pass (qh single, W split).
// Single fp16 out. grid (6, 64)
// ---------------------------------------------------------------------------
__global__ __launch_bounds__(256, 2) void k_gemm_query(const float* __restrict__ bias) {
    float acc[4][4][4] = {};
    const size_t aoff = (size_t)blockIdx.y * 128 * DIM;
    const size_t boff = (size_t)blockIdx.x * 128 * DIM;
    mainloop2(g_qhh + aoff, DIM, g_wh + boff, g_wl + boff, DIM, DIM / CHUNK, acc);

    const int lane = threadIdx.x & 31, wid = threadIdx.x >> 5;
    const int wm = wid & 1, wn = wid >> 1;
    const int gr = lane >> 2, gc = (lane & 3) * 2;
    const int row0 = blockIdx.y * 128 + wm * 64, col0 = blockIdx.x * 128 + wn * 32;
    #pragma unroll
    for (int tn = 0; tn < 4; tn++) {
        const int c = col0 + tn * 8 + gc;
        const float2 bb = *reinterpret_cast<const float2*>(bias + c);
        #pragma unroll
        for (int tm = 0; tm < 4; tm++)
            #pragma unroll
            for (int hf = 0; hf < 2; hf++) {
                const int r = row0 + tm * 16 + gr + hf * 8;
                float v0 = acc[tm][tn][hf * 2 + 0] + bb.x;
                float v1 = acc[tm][tn][hf * 2 + 1] + bb.y;
                *reinterpret_cast<uint32_t*>(&g_qryh[(size_t)r * DIM + c]) =
                    packh(__float2half_rn(v0), __float2half_rn(v1));
            }
    }
}

// ---------------------------------------------------------------------------
// GEMM 2: scores = SCALE * ch . query^T; mask -> -1e30; 1-pass. grid (8, 16, 8)
// ---------------------------------------------------------------------------
__global__ __launch_bounds__(256, 2) void k_gemm_scores(const int* __restrict__ qmask) {
    float acc[4][4][4] = {};
    const int z = blockIdx.z;
    const size_t aoff = (size_t)z * LC * DIM + (size_t)blockIdx.y * 128 * DIM;
    const size_t boff = (size_t)z * LQ * DIM + (size_t)blockIdx.x * 128 * DIM;
    mainloop1(g_chh + aoff, DIM, g_qryh + boff, DIM, DIM / CHUNK, acc);

    const int lane = threadIdx.x & 31, wid = threadIdx.x >> 5;
    const int wm = wid & 1, wn = wid >> 1;
    const int gr = lane >> 2, gc = (lane & 3) * 2;
    const int row0 = blockIdx.y * 128 + wm * 64, col0 = blockIdx.x * 128 + wn * 32;
    float* sbase = g_scores + (size_t)z * LC * LQ;
    const int* mrow = qmask + (size_t)z * LQ;
    #pragma unroll
    for (int tn = 0; tn < 4; tn++) {
        const int c = col0 + tn * 8 + gc;
        const int2 mk = *reinterpret_cast<const int2*>(mrow + c);
        #pragma unroll
        for (int tm = 0; tm < 4; tm++)
            #pragma unroll
            for (int hf = 0; hf < 2; hf++) {
                const int r = row0 + tm * 16 + gr + hf * 8;
                float2 v;
                v.x = mk.x ? acc[tm][tn][hf * 2 + 0] * SCALE_F : NEG_INF;
                v.y = mk.y ? acc[tm][tn][hf * 2 + 1] * SCALE_F : NEG_INF;
                *reinterpret_cast<float2*>(sbase + (size_t)r * LQ + c) = v;
            }
    }
}

// ---------------------------------------------------------------------------
// GEMM 3: attn = P . qh^T; 1-pass (both single). grid (6, 16, 8)
// ---------------------------------------------------------------------------
__global__ __launch_bounds__(256, 2) void k_gemm_out(float* __restrict__ out) {
    float acc[4][4][4] = {};
    const int z = blockIdx.z;
    const size_t aoff = (size_t)z * LC * LQ + (size_t)blockIdx.y * 128 * LQ;
    const size_t boff = (size_t)z * DIM * LQ + (size_t)blockIdx.x * 128 * LQ;
    mainloop1(g_ph + aoff, LQ, g_qth + boff, LQ, LQ / CHUNK, acc);

    const int lane = threadIdx.x & 31, wid = threadIdx.x >> 5;
    const int wm = wid & 1, wn = wid >> 1;
    const int gr = lane >> 2, gc = (lane & 3) * 2;
    const int row0 = blockIdx.y * 128 + wm * 64, col0 = blockIdx.x * 128 + wn * 32;
    float* obase = out + (size_t)z * LC * ODIM + DIM;
    #pragma unroll
    for (int tn = 0; tn < 4; tn++) {
        const int c = col0 + tn * 8 + gc;
        #pragma unroll
        for (int tm = 0; tm < 4; tm++)
            #pragma unroll
            for (int hf = 0; hf < 2; hf++) {
                const int r = row0 + tm * 16 + gr + hf * 8;
                float2 v = make_float2(acc[tm][tn][hf * 2 + 0], acc[tm][tn][hf * 2 + 1]);
                *reinterpret_cast<float2*>(obase + (size_t)r * ODIM + c) = v;
            }
    }
}

// ---------------------------------------------------------------------------
// Prep: ch -> out[0:768] copy + fp16 single
// ---------------------------------------------------------------------------
__global__ __launch_bounds__(256) void k_prep_ch(const float* __restrict__ ch,
                                                 float* __restrict__ out) {
    const size_t total4 = (size_t)BATCH * LC * (DIM / 4);
    for (size_t i = (size_t)blockIdx.x * blockDim.x + threadIdx.x; i < total4;
         i += (size_t)gridDim.x * blockDim.x) {
        float4 x = reinterpret_cast<const float4*>(ch)[i];
        size_t row = i / (DIM / 4);
        size_t d4 = i % (DIM / 4);
        reinterpret_cast<float4*>(out)[row * (ODIM / 4) + d4] = x;
        reinterpret_cast<uint2*>(g_chh)[i] =
            make_uint2(packh(__float2half_rn(x.x), __float2half_rn(x.y)),
                       packh(__float2half_rn(x.z), __float2half_rn(x.w)));
    }
}

// ---------------------------------------------------------------------------
// Prep: qh -> row-major single (qhh) + transposed single (qth)
// grid (24, 32, 8), block (32, 8)
// ---------------------------------------------------------------------------
__global__ __launch_bounds__(256) void k_prep_q(const float* __restrict__ qh) {
    __shared__ float t[32][33];
    int z = blockIdx.z;
    int d0 = blockIdx.x * 32, q0 = blockIdx.y * 32;
    const float* src = qh + (size_t)z * LQ * DIM;
    int tx = threadIdx.x, ty = threadIdx.y;
    __half* rh = g_qhh + (size_t)z * LQ * DIM;
    #pragma unroll
    for (int i = 0; i < 4; i++) {
        int q = q0 + ty + 8 * i;
        float v = src[(size_t)q * DIM + d0 + tx];
        t[ty + 8 * i][tx] = v;
        rh[(size_t)q * DIM + d0 + tx] = __float2half_rn(v);
    }
    __syncthreads();
    __half* dh = g_qth + (size_t)z * DIM * LQ;
    #pragma unroll
    for (int i = 0; i < 4; i++) {
        float v = t[tx][ty + 8 * i];
        dh[(size_t)(d0 + ty + 8 * i) * LQ + q0 + tx] = __float2half_rn(v);
    }
}

// ---------------------------------------------------------------------------
// W split
// ---------------------------------------------------------------------------
__global__ __launch_bounds__(256) void k_split_w(const float* __restrict__ src, int n4) {
    int i = blockIdx.x * blockDim.x + threadIdx.x;
    if (i >= n4) return;
    float4 x = reinterpret_cast<const float4*>(src)[i];
    __half h0, h1, h2, h3, l0, l1, l2, l3;
    split2h(x.x, h0, l0); split2h(x.y, h1, l1);
    split2h(x.z, h2, l2); split2h(x.w, h3, l3);
    reinterpret_cast<uint2*>(g_wh)[i] = make_uint2(packh(h0, h1), packh(h2, h3));
    reinterpret_cast<uint2*>(g_wl)[i] = make_uint2(packh(l0, l1), packh(l2, l3));
}

// ---------------------------------------------------------------------------
// Row softmax over Lq=1024; fp32 in, P fp16 single out. grid 16384 x 256
// ---------------------------------------------------------------------------
__global__ __launch_bounds__(256) void k_softmax() {
    const size_t rowoff = (size_t)blockIdx.x * LQ;
    const float* p = g_scores + rowoff;
    const int t = threadIdx.x;
    float4 v = reinterpret_cast<const float4*>(p)[t];

    __shared__ float red[8];
    float m = fmaxf(fmaxf(v.x, v.y), fmaxf(v.z, v.w));
    #pragma unroll
    for (int o = 16; o; o >>= 1) m = fmaxf(m, __shfl_xor_sync(0xffffffffu, m, o));
    if ((t & 31) == 0) red[t >> 5] = m;
    __syncthreads();
    m = red[0];
    #pragma unroll
    for (int w = 1; w < 8; w++) m = fmaxf(m, red[w]);
    __syncthreads();

    v.x = __expf(v.x - m); v.y = __expf(v.y - m);
    v.z = __expf(v.z - m); v.w = __expf(v.w - m);
    float s = v.x + v.y + v.z + v.w;
    #pragma unroll
    for (int o = 16; o; o >>= 1) s += __shfl_xor_sync(0xffffffffu, s, o);
    if ((t & 31) == 0) red[t >> 5] = s;
    __syncthreads();
    s = red[0];
    #pragma unroll
    for (int w = 1; w < 8; w++) s += red[w];

    float inv = 1.0f / s;
    v.x *= inv; v.y *= inv; v.z *= inv; v.w *= inv;

    reinterpret_cast<uint2*>(g_ph + rowoff)[t] =
        make_uint2(packh(__float2half_rn(v.x), __float2half_rn(v.y)),
                   packh(__float2half_rn(v.z), __float2half_rn(v.w)));
}

// ---------------------------------------------------------------------------
extern "C" void kernel_launch(void* const* d_in, const int* in_sizes, int n_in,
                              void* d_out, int out_size) {
    const float* ch    = (const float*)d_in[0];
    const float* qh    = (const float*)d_in[2];
    const int*   qmask = (const int*)d_in[3];
    const float* W     = (const float*)d_in[4];
    const float* bias  = (const float*)d_in[5];
    float*       out   = (float*)d_out;

    cudaFuncSetAttribute(k_gemm_query, cudaFuncAttributeMaxDynamicSharedMemorySize, SMEM_DYN2);
    cudaFuncSetAttribute(k_gemm_scores, cudaFuncAttributeMaxDynamicSharedMemorySize, SMEM_DYN3);
    cudaFuncSetAttribute(k_gemm_out, cudaFuncAttributeMaxDynamicSharedMemorySize, SMEM_DYN3);

    int n4_w = DIM * DIM / 4;
    k_prep_q<<<dim3(DIM / 32, LQ / 32, BATCH), dim3(32, 8)>>>(qh);
    k_split_w<<<(n4_w + 255) / 256, 256>>>(W, n4_w);
    k_gemm_query<<<dim3(DIM / 128, BATCH * LQ / 128), 256, SMEM_DYN2>>>(bias);
    k_prep_ch<<<1184, 256>>>(ch, out);
    k_gemm_scores<<<dim3(LQ / 128, LC / 128, BATCH), 256, SMEM_DYN3>>>(qmask);
    k_softmax<<<BATCH * LC, 256>>>();
    k_gemm_out<<<dim3(DIM / 128, LC / 128, BATCH), 256, SMEM_DYN3>>>(out);
}

// round 15
// speedup vs baseline: 2.2137x; 1.0697x over previous
#include <cuda_runtime.h>
#include <cuda_fp16.h>
#include <cstdint>

#define BATCH 8
#define LC    2048
#define LQ    1024
#define DIM   768
#define ODIM  1536

#define NEG_INF (-1e30f)
#define SCALE_F 0.03608439182435161f  // 1/sqrt(768)

// ---------------------------------------------------------------------------
// Scratch (__device__ globals; allocation-free rule). fp16 operands.
// Compacted question axis: per batch, valid q's packed to front, padded to 128.
// ---------------------------------------------------------------------------
__device__ __align__(16) __half g_chh[(size_t)BATCH * LC * DIM];    // ch fp16
__device__ __align__(16) __half g_cqh[(size_t)BATCH * LQ * DIM];    // compacted qh rows
__device__ __align__(16) __half g_cqt[(size_t)BATCH * DIM * LQ];    // compacted qh^T
__device__ __align__(16) __half g_wh[DIM * DIM];                    // W fp16
__device__ __align__(16) __half g_qry[(size_t)BATCH * LQ * DIM];    // compacted query
__device__ __align__(16) float  g_scores[(size_t)BATCH * LC * LQ];  // first nv128 cols
__device__ __align__(16) __half g_ph[(size_t)BATCH * LC * LQ];      // compacted P
__device__ int g_nv[BATCH];
__device__ int g_nv128[BATCH];
__device__ int g_cidx[BATCH * LQ];

// ---------------------------------------------------------------------------
// helpers
// ---------------------------------------------------------------------------
static __device__ __forceinline__ uint32_t smem_u32(const void* p) {
    uint32_t r;
    asm("{ .reg .u64 t; cvta.to.shared.u64 t, %1; cvt.u32.u64 %0, t; }"
        : "=r"(r) : "l"(p));
    return r;
}
static __device__ __forceinline__ void cp16(uint32_t dst, const void* src) {
    asm volatile("cp.async.cg.shared.global [%0], [%1], 16;" :: "r"(dst), "l"(src));
}
static __device__ __forceinline__ uint32_t packh(__half a, __half b) {
    __half2 t = __halves2half2(a, b);
    return *reinterpret_cast<uint32_t*>(&t);
}

#define LDSM_X4(r0, r1, r2, r3, addr) \
    asm volatile("ldmatrix.sync.aligned.m8n8.x4.shared.b16 {%0,%1,%2,%3}, [%4];" \
                 : "=r"(r0), "=r"(r1), "=r"(r2), "=r"(r3) : "r"(addr))

#define MMA16816(d, a, b) \
    asm volatile("mma.sync.aligned.m16n8k16.row.col.f32.f16.f16.f32 " \
                 "{%0,%1,%2,%3}, {%4,%5,%6,%7}, {%8,%9}, {%0,%1,%2,%3};" \
                 : "+f"((d)[0]), "+f"((d)[1]), "+f"((d)[2]), "+f"((d)[3]) \
                 : "r"((a)[0]), "r"((a)[1]), "r"((a)[2]), "r"((a)[3]), \
                   "r"((b)[0]), "r"((b)[1]))

// ---------------------------------------------------------------------------
// Single fp16 tile: 128 rows x 64B (32 fp16 per 32-k chunk), swizzled.
// ---------------------------------------------------------------------------
#define CHUNK 32
#define NTILE_B 8192
#define STAGE_B (2 * NTILE_B)   // A + B per stage = 16KB; 4 stages = 64KB
#define SMEM_DYN 65536

static __device__ __forceinline__ uint32_t swz64(uint32_t row, uint32_t kb) {
    return row * 64 + (kb ^ (((row >> 1) & 3) << 4));
}

static __device__ __forceinline__ void load_single(uint32_t tb,
    const __half* __restrict__ H, int ld, int k0, int tid) {
    #pragma unroll
    for (int i = 0; i < 2; i++) {
        int idx = tid + i * 256;
        int row = idx >> 2, seg = idx & 3;
        cp16(tb + swz64(row, seg * 16), (const void*)(H + (size_t)row * ld + k0 + seg * 8));
    }
}

// ---- compute: 1-pass (A single + B single), warp tile 64x32 ----
static __device__ __forceinline__ void compute1(uint32_t sb, int wm, int wn, int lane,
                                                float acc[4][4][4]) {
    const uint32_t tA = sb, tB = sb + NTILE_B;
    #pragma unroll
    for (int ks = 0; ks < 2; ks++) {
        const uint32_t akb = ks * 32 + ((lane >> 4) << 4);
        const uint32_t arow = wm * 64 + (lane & 15);
        uint32_t a[4][4];
        #pragma unroll
        for (int tm = 0; tm < 4; tm++)
            LDSM_X4(a[tm][0], a[tm][1], a[tm][2], a[tm][3], tA + swz64(arow + tm * 16, akb));
        const uint32_t brow = wn * 32 + (lane & 7) + ((lane >> 4) << 3);
        const uint32_t bkb = ks * 32 + (((lane >> 3) & 1) << 4);
        uint32_t b[4][2];
        #pragma unroll
        for (int tp = 0; tp < 2; tp++) {
            uint32_t t0, t1, t2, t3;
            LDSM_X4(t0, t1, t2, t3, tB + swz64(brow + tp * 16, bkb));
            b[tp * 2][0] = t0; b[tp * 2][1] = t1;
            b[tp * 2 + 1][0] = t2; b[tp * 2 + 1][1] = t3;
        }
        #pragma unroll
        for (int tm = 0; tm < 4; tm++)
            #pragma unroll
            for (int tn = 0; tn < 4; tn++)
                MMA16816(acc[tm][tn], a[tm], b[tn]);
    }
}

// ---- mainloop: 4-stage cp.async pipeline, one __syncthreads per chunk ----
static __device__ __forceinline__ void mainloop1(
    const __half* A, int ldA, const __half* B, int ldB, int nk, float acc[4][4][4]) {
    extern __shared__ char smem[];
    const uint32_t sb = smem_u32(smem);
    const int tid = threadIdx.x, lane = tid & 31, wid = tid >> 5;
    const int wm = wid & 1, wn = wid >> 1;

    #pragma unroll
    for (int p = 0; p < 3; p++) {
        uint32_t st = sb + p * STAGE_B;
        load_single(st, A, ldA, p * CHUNK, tid);
        load_single(st + NTILE_B, B, ldB, p * CHUNK, tid);
        asm volatile("cp.async.commit_group;" ::: "memory");
    }
    for (int k = 0; k < nk; k++) {
        if (k + 2 < nk)      asm volatile("cp.async.wait_group 2;" ::: "memory");
        else if (k + 1 < nk) asm volatile("cp.async.wait_group 1;" ::: "memory");
        else                 asm volatile("cp.async.wait_group 0;" ::: "memory");
        __syncthreads();
        if (k + 3 < nk) {
            uint32_t st = sb + ((k + 3) & 3) * STAGE_B;
            load_single(st, A, ldA, (k + 3) * CHUNK, tid);
            load_single(st + NTILE_B, B, ldB, (k + 3) * CHUNK, tid);
            asm volatile("cp.async.commit_group;" ::: "memory");
        }
        compute1(sb + (k & 3) * STAGE_B, wm, wn, lane, acc);
    }
}

// ---------------------------------------------------------------------------
// Mask scan: per batch prefix-sum -> cidx (compacted index), nv, nv128
// grid BATCH, block 1024
// ---------------------------------------------------------------------------
__global__ __launch_bounds__(1024) void k_scan(const int* __restrict__ qmask) {
    __shared__ int s[1024];
    const int b = blockIdx.x, t = threadIdx.x;
    const int m = qmask[b * LQ + t] ? 1 : 0;
    s[t] = m;
    __syncthreads();
    #pragma unroll
    for (int off = 1; off < 1024; off <<= 1) {
        int v = (t >= off) ? s[t - off] : 0;
        __syncthreads();
        s[t] += v;
        __syncthreads();
    }
    if (m) g_cidx[b * LQ + s[t] - 1] = t;
    if (t == 1023) {
        g_nv[b] = s[1023];
        g_nv128[b] = (s[1023] + 127) & ~127;
    }
}

// ---------------------------------------------------------------------------
// Gather qh into compacted row-major (cqh) + compacted transposed (cqt), fp16.
// Pads with zeros to the full 1024 compacted slots.
// grid (24, 32, 8), block (32, 8)
// ---------------------------------------------------------------------------
__global__ __launch_bounds__(256) void k_gather(const float* __restrict__ qh) {
    __shared__ float tt[32][33];
    __shared__ int sci[32];
    const int z = blockIdx.z;
    const int d0 = blockIdx.x * 32, q0 = blockIdx.y * 32;
    const int tx = threadIdx.x, ty = threadIdx.y;
    const int nv = g_nv[z];
    if (ty == 0) {
        int q = q0 + tx;
        sci[tx] = (q < nv) ? g_cidx[z * LQ + q] : -1;
    }
    __syncthreads();
    const float* src = qh + (size_t)z * LQ * DIM;
    __half* cqh = g_cqh + (size_t)z * LQ * DIM;
    #pragma unroll
    for (int i = 0; i < 4; i++) {
        int j = ty + 8 * i;
        int row = sci[j];
        float v = (row >= 0) ? src[(size_t)row * DIM + d0 + tx] : 0.0f;
        tt[j][tx] = v;
        cqh[(size_t)(q0 + j) * DIM + d0 + tx] = __float2half_rn(v);
    }
    __syncthreads();
    __half* cqt = g_cqt + (size_t)z * DIM * LQ;
    #pragma unroll
    for (int i = 0; i < 4; i++)
        cqt[(size_t)(d0 + ty + 8 * i) * LQ + q0 + tx] = __float2half_rn(tt[tx][ty + 8 * i]);
}

// ---------------------------------------------------------------------------
// W -> fp16 single
// ---------------------------------------------------------------------------
__global__ __launch_bounds__(256) void k_conv_w(const float* __restrict__ src, int n4) {
    int i = blockIdx.x * blockDim.x + threadIdx.x;
    if (i >= n4) return;
    float4 x = reinterpret_cast<const float4*>(src)[i];
    reinterpret_cast<uint2*>(g_wh)[i] =
        make_uint2(packh(__float2half_rn(x.x), __float2half_rn(x.y)),
                   packh(__float2half_rn(x.z), __float2half_rn(x.w)));
}

// ---------------------------------------------------------------------------
// Prep: ch -> out[0:768] copy + fp16
// ---------------------------------------------------------------------------
__global__ __launch_bounds__(256) void k_prep_ch(const float* __restrict__ ch,
                                                 float* __restrict__ out) {
    const size_t total4 = (size_t)BATCH * LC * (DIM / 4);
    for (size_t i = (size_t)blockIdx.x * blockDim.x + threadIdx.x; i < total4;
         i += (size_t)gridDim.x * blockDim.x) {
        float4 x = reinterpret_cast<const float4*>(ch)[i];
        size_t row = i / (DIM / 4);
        size_t d4 = i % (DIM / 4);
        reinterpret_cast<float4*>(out)[row * (ODIM / 4) + d4] = x;
        reinterpret_cast<uint2*>(g_chh)[i] =
            make_uint2(packh(__float2half_rn(x.x), __float2half_rn(x.y)),
                       packh(__float2half_rn(x.z), __float2half_rn(x.w)));
    }
}

// ---------------------------------------------------------------------------
// GEMM 1: query[j,e] = cqh[j,:] . W[e,:] + b[e]; 1-pass. grid (6, 8, 8)
// Only compacted rows [0, nv128) computed.
// ---------------------------------------------------------------------------
__global__ __launch_bounds__(256, 2) void k_gemm_query(const float* __restrict__ bias) {
    const int z = blockIdx.z;
    const int nv128 = g_nv128[z];
    if ((int)blockIdx.y * 128 >= nv128) return;
    float acc[4][4][4] = {};
    const __half* A = g_cqh + (size_t)z * LQ * DIM + (size_t)blockIdx.y * 128 * DIM;
    const __half* B = g_wh + (size_t)blockIdx.x * 128 * DIM;
    mainloop1(A, DIM, B, DIM, DIM / CHUNK, acc);

    const int lane = threadIdx.x & 31, wid = threadIdx.x >> 5;
    const int wm = wid & 1, wn = wid >> 1;
    const int gr = lane >> 2, gc = (lane & 3) * 2;
    const int row0 = blockIdx.y * 128 + wm * 64, col0 = blockIdx.x * 128 + wn * 32;
    __half* qry = g_qry + (size_t)z * LQ * DIM;
    #pragma unroll
    for (int tn = 0; tn < 4; tn++) {
        const int c = col0 + tn * 8 + gc;
        const float2 bb = *reinterpret_cast<const float2*>(bias + c);
        #pragma unroll
        for (int tm = 0; tm < 4; tm++)
            #pragma unroll
            for (int hf = 0; hf < 2; hf++) {
                const int r = row0 + tm * 16 + gr + hf * 8;
                float v0 = acc[tm][tn][hf * 2 + 0] + bb.x;
                float v1 = acc[tm][tn][hf * 2 + 1] + bb.y;
                *reinterpret_cast<uint32_t*>(&qry[(size_t)r * DIM + c]) =
                    packh(__float2half_rn(v0), __float2half_rn(v1));
            }
    }
}

// ---------------------------------------------------------------------------
// GEMM 2: scores[c, j] = SCALE * ch[c,:] . query[j,:]; j >= nv -> NEG_INF.
// 1-pass, compacted q. grid (8, 16, 8)
// ---------------------------------------------------------------------------
__global__ __launch_bounds__(256, 2) void k_gemm_scores() {
    const int z = blockIdx.z;
    const int nv128 = g_nv128[z];
    if ((int)blockIdx.x * 128 >= nv128) return;
    const int nv = g_nv[z];
    float acc[4][4][4] = {};
    const __half* A = g_chh + (size_t)z * LC * DIM + (size_t)blockIdx.y * 128 * DIM;
    const __half* B = g_qry + (size_t)z * LQ * DIM + (size_t)blockIdx.x * 128 * DIM;
    mainloop1(A, DIM, B, DIM, DIM / CHUNK, acc);

    const int lane = threadIdx.x & 31, wid = threadIdx.x >> 5;
    const int wm = wid & 1, wn = wid >> 1;
    const int gr = lane >> 2, gc = (lane & 3) * 2;
    const int row0 = blockIdx.y * 128 + wm * 64, col0 = blockIdx.x * 128 + wn * 32;
    float* sbase = g_scores + (size_t)z * LC * LQ;
    #pragma unroll
    for (int tn = 0; tn < 4; tn++) {
        const int c = col0 + tn * 8 + gc;
        #pragma unroll
        for (int tm = 0; tm < 4; tm++)
            #pragma unroll
            for (int hf = 0; hf < 2; hf++) {
                const int r = row0 + tm * 16 + gr + hf * 8;
                float2 v;
                v.x = (c + 0 < nv) ? acc[tm][tn][hf * 2 + 0] * SCALE_F : NEG_INF;
                v.y = (c + 1 < nv) ? acc[tm][tn][hf * 2 + 1] * SCALE_F : NEG_INF;
                *reinterpret_cast<float2*>(sbase + (size_t)r * LQ + c) = v;
            }
    }
}

// ---------------------------------------------------------------------------
// Row softmax over compacted width nv128; fp32 in, P fp16 out. grid 16384 x 256
// ---------------------------------------------------------------------------
__global__ __launch_bounds__(256) void k_softmax() {
    const int b = blockIdx.x >> 11;  // / LC
    const int n4 = g_nv128[b] >> 2;
    const size_t rowoff = (size_t)blockIdx.x * LQ;
    const int t = threadIdx.x;
    const bool act = t < n4;
    float4 v = act ? reinterpret_cast<const float4*>(g_scores + rowoff)[t]
                   : make_float4(NEG_INF, NEG_INF, NEG_INF, NEG_INF);

    __shared__ float red[8];
    float m = fmaxf(fmaxf(v.x, v.y), fmaxf(v.z, v.w));
    #pragma unroll
    for (int o = 16; o; o >>= 1) m = fmaxf(m, __shfl_xor_sync(0xffffffffu, m, o));
    if ((t & 31) == 0) red[t >> 5] = m;
    __syncthreads();
    m = red[0];
    #pragma unroll
    for (int w = 1; w < 8; w++) m = fmaxf(m, red[w]);
    __syncthreads();

    v.x = __expf(v.x - m); v.y = __expf(v.y - m);
    v.z = __expf(v.z - m); v.w = __expf(v.w - m);
    float s = v.x + v.y + v.z + v.w;
    #pragma unroll
    for (int o = 16; o; o >>= 1) s += __shfl_xor_sync(0xffffffffu, s, o);
    if ((t & 31) == 0) red[t >> 5] = s;
    __syncthreads();
    s = red[0];
    #pragma unroll
    for (int w = 1; w < 8; w++) s += red[w];

    float inv = 1.0f / s;
    v.x *= inv; v.y *= inv; v.z *= inv; v.w *= inv;

    if (act)
        reinterpret_cast<uint2*>(g_ph + rowoff)[t] =
            make_uint2(packh(__float2half_rn(v.x), __float2half_rn(v.y)),
                       packh(__float2half_rn(v.z), __float2half_rn(v.w)));
}

// ---------------------------------------------------------------------------
// GEMM 3: attn[c, d] = P[c, :nv128] . cqt[d, :nv128]; 1-pass. grid (6, 16, 8)
// ---------------------------------------------------------------------------
__global__ __launch_bounds__(256, 2) void k_gemm_out(float* __restrict__ out) {
    const int z = blockIdx.z;
    const int nk = g_nv128[z] >> 5;   // >= 4
    float acc[4][4][4] = {};
    const __half* A = g_ph + (size_t)z * LC * LQ + (size_t)blockIdx.y * 128 * LQ;
    const __half* B = g_cqt + (size_t)z * DIM * LQ + (size_t)blockIdx.x * 128 * LQ;
    mainloop1(A, LQ, B, LQ, nk, acc);

    const int lane = threadIdx.x & 31, wid = threadIdx.x >> 5;
    const int wm = wid & 1, wn = wid >> 1;
    const int gr = lane >> 2, gc = (lane & 3) * 2;
    const int row0 = blockIdx.y * 128 + wm * 64, col0 = blockIdx.x * 128 + wn * 32;
    float* obase = out + (size_t)z * LC * ODIM + DIM;
    #pragma unroll
    for (int tn = 0; tn < 4; tn++) {
        const int c = col0 + tn * 8 + gc;
        #pragma unroll
        for (int tm = 0; tm < 4; tm++)
            #pragma unroll
            for (int hf = 0; hf < 2; hf++) {
                const int r = row0 + tm * 16 + gr + hf * 8;
                float2 v = make_float2(acc[tm][tn][hf * 2 + 0], acc[tm][tn][hf * 2 + 1]);
                *reinterpret_cast<float2*>(obase + (size_t)r * ODIM + c) = v;
            }
    }
}

// ---------------------------------------------------------------------------
extern "C" void kernel_launch(void* const* d_in, const int* in_sizes, int n_in,
                              void* d_out, int out_size) {
    const float* ch    = (const float*)d_in[0];
    const float* qh    = (const float*)d_in[2];
    const int*   qmask = (const int*)d_in[3];
    const float* W     = (const float*)d_in[4];
    const float* bias  = (const float*)d_in[5];
    float*       out   = (float*)d_out;

    cudaFuncSetAttribute(k_gemm_query, cudaFuncAttributeMaxDynamicSharedMemorySize, SMEM_DYN);
    cudaFuncSetAttribute(k_gemm_scores, cudaFuncAttributeMaxDynamicSharedMemorySize, SMEM_DYN);
    cudaFuncSetAttribute(k_gemm_out, cudaFuncAttributeMaxDynamicSharedMemorySize, SMEM_DYN);

    int n4_w = DIM * DIM / 4;
    k_scan<<<BATCH, 1024>>>(qmask);
    k_conv_w<<<(n4_w + 255) / 256, 256>>>(W, n4_w);
    k_gather<<<dim3(DIM / 32, LQ / 32, BATCH), dim3(32, 8)>>>(qh);
    k_gemm_query<<<dim3(DIM / 128, LQ / 128, BATCH), 256, SMEM_DYN>>>(bias);
    k_prep_ch<<<1184, 256>>>(ch, out);
    k_gemm_scores<<<dim3(LQ / 128, LC / 128, BATCH), 256, SMEM_DYN>>>();
    k_softmax<<<BATCH * LC, 256>>>();
    k_gemm_out<<<dim3(DIM / 128, LC / 128, BATCH), 256, SMEM_DYN>>>(out);
}

// round 16
// speedup vs baseline: 3.3440x; 1.5106x over previous
#include <cuda_runtime.h>
#include <cuda_fp16.h>
#include <cstdint>

#define BATCH 8
#define LC    2048
#define LQ    1024
#define DIM   768
#define ODIM  1536

#define NEG_INF (-1e30f)
#define SCALE_F 0.03608439182435161f  // 1/sqrt(768)

// ---------------------------------------------------------------------------
// Scratch (__device__ globals; allocation-free rule). fp16 operands.
// Compacted question axis: per batch, valid q's packed to front, padded to 128.
// ---------------------------------------------------------------------------
__device__ __align__(16) __half g_chh[(size_t)BATCH * LC * DIM];    // ch fp16
__device__ __align__(16) __half g_cqh[(size_t)BATCH * LQ * DIM];    // compacted qh rows
__device__ __align__(16) __half g_cqt[(size_t)BATCH * DIM * LQ];    // compacted qh^T
__device__ __align__(16) __half g_wh[DIM * DIM];                    // W fp16
__device__ __align__(16) __half g_qry[(size_t)BATCH * LQ * DIM];    // compacted query
__device__ __align__(16) float  g_scores[(size_t)BATCH * LC * LQ];  // first nv128 cols
__device__ __align__(16) __half g_ph[(size_t)BATCH * LC * LQ];      // compacted P
__device__ int g_nv[BATCH];
__device__ int g_nv128[BATCH];
__device__ int g_cidx[BATCH * LQ];

// ---------------------------------------------------------------------------
// helpers
// ---------------------------------------------------------------------------
static __device__ __forceinline__ uint32_t smem_u32(const void* p) {
    uint32_t r;
    asm("{ .reg .u64 t; cvta.to.shared.u64 t, %1; cvt.u32.u64 %0, t; }"
        : "=r"(r) : "l"(p));
    return r;
}
static __device__ __forceinline__ void cp16(uint32_t dst, const void* src) {
    asm volatile("cp.async.cg.shared.global [%0], [%1], 16;" :: "r"(dst), "l"(src));
}
static __device__ __forceinline__ uint32_t packh(__half a, __half b) {
    __half2 t = __halves2half2(a, b);
    return *reinterpret_cast<uint32_t*>(&t);
}

#define LDSM_X4(r0, r1, r2, r3, addr) \
    asm volatile("ldmatrix.sync.aligned.m8n8.x4.shared.b16 {%0,%1,%2,%3}, [%4];" \
                 : "=r"(r0), "=r"(r1), "=r"(r2), "=r"(r3) : "r"(addr))

#define MMA16816(d, a, b) \
    asm volatile("mma.sync.aligned.m16n8k16.row.col.f32.f16.f16.f32 " \
                 "{%0,%1,%2,%3}, {%4,%5,%6,%7}, {%8,%9}, {%0,%1,%2,%3};" \
                 : "+f"((d)[0]), "+f"((d)[1]), "+f"((d)[2]), "+f"((d)[3]) \
                 : "r"((a)[0]), "r"((a)[1]), "r"((a)[2]), "r"((a)[3]), \
                   "r"((b)[0]), "r"((b)[1]))

// ---------------------------------------------------------------------------
// Tile: 128 rows x 128B (64 fp16 per 64-k chunk), XOR-swizzled (conflict-free
// for both cp.async stores and ldmatrix loads; proven in earlier rounds).
// ---------------------------------------------------------------------------
#define CHUNK 64
#define TILE_B  16384
#define STAGE_B (2 * TILE_B)    // A + B per stage = 32KB; 3 stages = 96KB
#define SMEM_DYN 98304

static __device__ __forceinline__ uint32_t swz128(uint32_t row, uint32_t kb) {
    return (row * 128 + kb) ^ ((row & 7) << 4);
}

static __device__ __forceinline__ void load_tile(uint32_t tb,
    const __half* __restrict__ H, int ld, int k0, int tid) {
    #pragma unroll
    for (int i = 0; i < 4; i++) {
        int idx = tid + i * 256;           // 1024 segs: 128 rows x 8 x 16B
        int row = idx >> 3, seg = idx & 7;
        cp16(tb + swz128(row, seg * 16), (const void*)(H + (size_t)row * ld + k0 + seg * 8));
    }
}

// ---- compute one 64-k chunk; warp tile 64x32 ----
static __device__ __forceinline__ void compute64(uint32_t sb, int wm, int wn, int lane,
                                                 float acc[4][4][4]) {
    const uint32_t tA = sb, tB = sb + TILE_B;
    #pragma unroll
    for (int ks = 0; ks < 4; ks++) {
        const uint32_t akb = ks * 32 + ((lane >> 4) << 4);
        const uint32_t arow = wm * 64 + (lane & 15);
        uint32_t a[4][4];
        #pragma unroll
        for (int tm = 0; tm < 4; tm++)
            LDSM_X4(a[tm][0], a[tm][1], a[tm][2], a[tm][3],
                    tA + swz128(arow + tm * 16, akb));
        const uint32_t brow = wn * 32 + (lane & 7) + ((lane >> 4) << 3);
        const uint32_t bkb = ks * 32 + (((lane >> 3) & 1) << 4);
        uint32_t b[4][2];
        #pragma unroll
        for (int tp = 0; tp < 2; tp++) {
            uint32_t t0, t1, t2, t3;
            LDSM_X4(t0, t1, t2, t3, tB + swz128(brow + tp * 16, bkb));
            b[tp * 2][0] = t0; b[tp * 2][1] = t1;
            b[tp * 2 + 1][0] = t2; b[tp * 2 + 1][1] = t3;
        }
        #pragma unroll
        for (int tm = 0; tm < 4; tm++)
            #pragma unroll
            for (int tn = 0; tn < 4; tn++)
                MMA16816(acc[tm][tn], a[tm], b[tn]);
    }
}

// ---- mainloop: 3-stage cp.async pipeline, one __syncthreads per 64-k chunk ----
static __device__ __forceinline__ void mainloop(
    const __half* A, int ldA, const __half* B, int ldB, int nk, float acc[4][4][4]) {
    extern __shared__ char smem[];
    const uint32_t sb = smem_u32(smem);
    const int tid = threadIdx.x, lane = tid & 31, wid = tid >> 5;
    const int wm = wid & 1, wn = wid >> 1;

    #pragma unroll
    for (int p = 0; p < 2; p++) {
        uint32_t st = sb + p * STAGE_B;
        load_tile(st, A, ldA, p * CHUNK, tid);
        load_tile(st + TILE_B, B, ldB, p * CHUNK, tid);
        asm volatile("cp.async.commit_group;" ::: "memory");
    }
    for (int k = 0; k < nk; k++) {
        if (k + 1 < nk) asm volatile("cp.async.wait_group 1;" ::: "memory");
        else            asm volatile("cp.async.wait_group 0;" ::: "memory");
        __syncthreads();
        if (k + 2 < nk) {
            uint32_t st = sb + ((k + 2) % 3) * STAGE_B;
            load_tile(st, A, ldA, (k + 2) * CHUNK, tid);
            load_tile(st + TILE_B, B, ldB, (k + 2) * CHUNK, tid);
            asm volatile("cp.async.commit_group;" ::: "memory");
        }
        compute64(sb + (k % 3) * STAGE_B, wm, wn, lane, acc);
    }
}

// ---------------------------------------------------------------------------
// Mask scan: per batch prefix-sum -> cidx, nv, nv128. grid BATCH, block 1024
// ---------------------------------------------------------------------------
__global__ __launch_bounds__(1024) void k_scan(const int* __restrict__ qmask) {
    __shared__ int s[1024];
    const int b = blockIdx.x, t = threadIdx.x;
    const int m = qmask[b * LQ + t] ? 1 : 0;
    s[t] = m;
    __syncthreads();
    #pragma unroll
    for (int off = 1; off < 1024; off <<= 1) {
        int v = (t >= off) ? s[t - off] : 0;
        __syncthreads();
        s[t] += v;
        __syncthreads();
    }
    if (m) g_cidx[b * LQ + s[t] - 1] = t;
    if (t == 1023) {
        g_nv[b] = s[1023];
        g_nv128[b] = (s[1023] + 127) & ~127;
    }
}

// ---------------------------------------------------------------------------
// Gather qh into compacted row-major (cqh) + transposed (cqt), fp16, zero-pad.
// grid (24, 32, 8), block (32, 8)
// ---------------------------------------------------------------------------
__global__ __launch_bounds__(256) void k_gather(const float* __restrict__ qh) {
    __shared__ float tt[32][33];
    __shared__ int sci[32];
    const int z = blockIdx.z;
    const int d0 = blockIdx.x * 32, q0 = blockIdx.y * 32;
    const int tx = threadIdx.x, ty = threadIdx.y;
    const int nv = g_nv[z];
    if (ty == 0) {
        int q = q0 + tx;
        sci[tx] = (q < nv) ? g_cidx[z * LQ + q] : -1;
    }
    __syncthreads();
    const float* src = qh + (size_t)z * LQ * DIM;
    __half* cqh = g_cqh + (size_t)z * LQ * DIM;
    #pragma unroll
    for (int i = 0; i < 4; i++) {
        int j = ty + 8 * i;
        int row = sci[j];
        float v = (row >= 0) ? src[(size_t)row * DIM + d0 + tx] : 0.0f;
        tt[j][tx] = v;
        cqh[(size_t)(q0 + j) * DIM + d0 + tx] = __float2half_rn(v);
    }
    __syncthreads();
    __half* cqt = g_cqt + (size_t)z * DIM * LQ;
    #pragma unroll
    for (int i = 0; i < 4; i++)
        cqt[(size_t)(d0 + ty + 8 * i) * LQ + q0 + tx] = __float2half_rn(tt[tx][ty + 8 * i]);
}

// ---------------------------------------------------------------------------
// Fused prep: W -> fp16, and ch -> out[0:768] copy + fp16
// ---------------------------------------------------------------------------
__global__ __launch_bounds__(256) void k_prep(const float* __restrict__ W,
                                              const float* __restrict__ ch,
                                              float* __restrict__ out) {
    const size_t n4_w = DIM * DIM / 4;
    const size_t n4_ch = (size_t)BATCH * LC * (DIM / 4);
    const size_t total = n4_w + n4_ch;
    for (size_t i = (size_t)blockIdx.x * blockDim.x + threadIdx.x; i < total;
         i += (size_t)gridDim.x * blockDim.x) {
        if (i < n4_w) {
            float4 x = reinterpret_cast<const float4*>(W)[i];
            reinterpret_cast<uint2*>(g_wh)[i] =
                make_uint2(packh(__float2half_rn(x.x), __float2half_rn(x.y)),
                           packh(__float2half_rn(x.z), __float2half_rn(x.w)));
        } else {
            size_t j = i - n4_w;
            float4 x = reinterpret_cast<const float4*>(ch)[j];
            size_t row = j / (DIM / 4);
            size_t d4 = j % (DIM / 4);
            reinterpret_cast<float4*>(out)[row * (ODIM / 4) + d4] = x;
            reinterpret_cast<uint2*>(g_chh)[j] =
                make_uint2(packh(__float2half_rn(x.x), __float2half_rn(x.y)),
                           packh(__float2half_rn(x.z), __float2half_rn(x.w)));
        }
    }
}

// ---------------------------------------------------------------------------
// GEMM 1: query[j,e] = cqh[j,:] . W[e,:] + b[e]. grid (6, 8, 8)
// ---------------------------------------------------------------------------
__global__ __launch_bounds__(256, 2) void k_gemm_query(const float* __restrict__ bias) {
    const int z = blockIdx.z;
    const int nv128 = g_nv128[z];
    if ((int)blockIdx.y * 128 >= nv128) return;
    float acc[4][4][4] = {};
    const __half* A = g_cqh + (size_t)z * LQ * DIM + (size_t)blockIdx.y * 128 * DIM;
    const __half* B = g_wh + (size_t)blockIdx.x * 128 * DIM;
    mainloop(A, DIM, B, DIM, DIM / CHUNK, acc);

    const int lane = threadIdx.x & 31, wid = threadIdx.x >> 5;
    const int wm = wid & 1, wn = wid >> 1;
    const int gr = lane >> 2, gc = (lane & 3) * 2;
    const int row0 = blockIdx.y * 128 + wm * 64, col0 = blockIdx.x * 128 + wn * 32;
    __half* qry = g_qry + (size_t)z * LQ * DIM;
    #pragma unroll
    for (int tn = 0; tn < 4; tn++) {
        const int c = col0 + tn * 8 + gc;
        const float2 bb = *reinterpret_cast<const float2*>(bias + c);
        #pragma unroll
        for (int tm = 0; tm < 4; tm++)
            #pragma unroll
            for (int hf = 0; hf < 2; hf++) {
                const int r = row0 + tm * 16 + gr + hf * 8;
                float v0 = acc[tm][tn][hf * 2 + 0] + bb.x;
                float v1 = acc[tm][tn][hf * 2 + 1] + bb.y;
                *reinterpret_cast<uint32_t*>(&qry[(size_t)r * DIM + c]) =
                    packh(__float2half_rn(v0), __float2half_rn(v1));
            }
    }
}

// ---------------------------------------------------------------------------
// GEMM 2: scores[c, j] = SCALE * ch[c,:] . query[j,:]; j >= nv -> NEG_INF.
// grid (8, 16, 8)
// ---------------------------------------------------------------------------
__global__ __launch_bounds__(256, 2) void k_gemm_scores() {
    const int z = blockIdx.z;
    const int nv128 = g_nv128[z];
    if ((int)blockIdx.x * 128 >= nv128) return;
    const int nv = g_nv[z];
    float acc[4][4][4] = {};
    const __half* A = g_chh + (size_t)z * LC * DIM + (size_t)blockIdx.y * 128 * DIM;
    const __half* B = g_qry + (size_t)z * LQ * DIM + (size_t)blockIdx.x * 128 * DIM;
    mainloop(A, DIM, B, DIM, DIM / CHUNK, acc);

    const int lane = threadIdx.x & 31, wid = threadIdx.x >> 5;
    const int wm = wid & 1, wn = wid >> 1;
    const int gr = lane >> 2, gc = (lane & 3) * 2;
    const int row0 = blockIdx.y * 128 + wm * 64, col0 = blockIdx.x * 128 + wn * 32;
    float* sbase = g_scores + (size_t)z * LC * LQ;
    #pragma unroll
    for (int tn = 0; tn < 4; tn++) {
        const int c = col0 + tn * 8 + gc;
        #pragma unroll
        for (int tm = 0; tm < 4; tm++)
            #pragma unroll
            for (int hf = 0; hf < 2; hf++) {
                const int r = row0 + tm * 16 + gr + hf * 8;
                float2 v;
                v.x = (c + 0 < nv) ? acc[tm][tn][hf * 2 + 0] * SCALE_F : NEG_INF;
                v.y = (c + 1 < nv) ? acc[tm][tn][hf * 2 + 1] * SCALE_F : NEG_INF;
                *reinterpret_cast<float2*>(sbase + (size_t)r * LQ + c) = v;
            }
    }
}

// ---------------------------------------------------------------------------
// Row softmax over compacted width nv128; fp32 in, P fp16 out. grid 16384 x 256
// ---------------------------------------------------------------------------
__global__ __launch_bounds__(256) void k_softmax() {
    const int b = blockIdx.x >> 11;  // / LC
    const int n4 = g_nv128[b] >> 2;
    const size_t rowoff = (size_t)blockIdx.x * LQ;
    const int t = threadIdx.x;
    const bool act = t < n4;
    float4 v = act ? reinterpret_cast<const float4*>(g_scores + rowoff)[t]
                   : make_float4(NEG_INF, NEG_INF, NEG_INF, NEG_INF);

    __shared__ float red[8];
    float m = fmaxf(fmaxf(v.x, v.y), fmaxf(v.z, v.w));
    #pragma unroll
    for (int o = 16; o; o >>= 1) m = fmaxf(m, __shfl_xor_sync(0xffffffffu, m, o));
    if ((t & 31) == 0) red[t >> 5] = m;
    __syncthreads();
    m = red[0];
    #pragma unroll
    for (int w = 1; w < 8; w++) m = fmaxf(m, red[w]);
    __syncthreads();

    v.x = __expf(v.x - m); v.y = __expf(v.y - m);
    v.z = __expf(v.z - m); v.w = __expf(v.w - m);
    float s = v.x + v.y + v.z + v.w;
    #pragma unroll
    for (int o = 16; o; o >>= 1) s += __shfl_xor_sync(0xffffffffu, s, o);
    if ((t & 31) == 0) red[t >> 5] = s;
    __syncthreads();
    s = red[0];
    #pragma unroll
    for (int w = 1; w < 8; w++) s += red[w];

    float inv = 1.0f / s;
    v.x *= inv; v.y *= inv; v.z *= inv; v.w *= inv;

    if (act)
        reinterpret_cast<uint2*>(g_ph + rowoff)[t] =
            make_uint2(packh(__float2half_rn(v.x), __float2half_rn(v.y)),
                       packh(__float2half_rn(v.z), __float2half_rn(v.w)));
}

// ---------------------------------------------------------------------------
// GEMM 3: attn[c, d] = P[c, :nv128] . cqt[d, :nv128]. grid (6, 16, 8)
// nk = nv128/64 >= 2, matching the 2-deep prologue.
// ---------------------------------------------------------------------------
__global__ __launch_bounds__(256, 2) void k_gemm_out(float* __restrict__ out) {
    const int z = blockIdx.z;
    const int nk = g_nv128[z] >> 6;
    float acc[4][4][4] = {};
    const __half* A = g_ph + (size_t)z * LC * LQ + (size_t)blockIdx.y * 128 * LQ;
    const __half* B = g_cqt + (size_t)z * DIM * LQ + (size_t)blockIdx.x * 128 * LQ;
    mainloop(A, LQ, B, LQ, nk, acc);

    const int lane = threadIdx.x & 31, wid = threadIdx.x >> 5;
    const int wm = wid & 1, wn = wid >> 1;
    const int gr = lane >> 2, gc = (lane & 3) * 2;
    const int row0 = blockIdx.y * 128 + wm * 64, col0 = blockIdx.x * 128 + wn * 32;
    float* obase = out + (size_t)z * LC * ODIM + DIM;
    #pragma unroll
    for (int tn = 0; tn < 4; tn++) {
        const int c = col0 + tn * 8 + gc;
        #pragma unroll
        for (int tm = 0; tm < 4; tm++)
            #pragma unroll
            for (int hf = 0; hf < 2; hf++) {
                const int r = row0 + tm * 16 + gr + hf * 8;
                float2 v = make_float2(acc[tm][tn][hf * 2 + 0], acc[tm][tn][hf * 2 + 1]);
                *reinterpret_cast<float2*>(obase + (size_t)r * ODIM + c) = v;
            }
    }
}

// ---------------------------------------------------------------------------
extern "C" void kernel_launch(void* const* d_in, const int* in_sizes, int n_in,
                              void* d_out, int out_size) {
    const float* ch    = (const float*)d_in[0];
    const float* qh    = (const float*)d_in[2];
    const int*   qmask = (const int*)d_in[3];
    const float* W     = (const float*)d_in[4];
    const float* bias  = (const float*)d_in[5];
    float*       out   = (float*)d_out;

    cudaFuncSetAttribute(k_gemm_query, cudaFuncAttributeMaxDynamicSharedMemorySize, SMEM_DYN);
    cudaFuncSetAttribute(k_gemm_scores, cudaFuncAttributeMaxDynamicSharedMemorySize, SMEM_DYN);
    cudaFuncSetAttribute(k_gemm_out, cudaFuncAttributeMaxDynamicSharedMemorySize, SMEM_DYN);

    k_scan<<<BATCH, 1024>>>(qmask);
    k_gather<<<dim3(DIM / 32, LQ / 32, BATCH), dim3(32, 8)>>>(qh);
    k_prep<<<1200, 256>>>(W, ch, out);
    k_gemm_query<<<dim3(DIM / 128, LQ / 128, BATCH), 256, SMEM_DYN>>>(bias);
    k_gemm_scores<<<dim3(LQ / 128, LC / 128, BATCH), 256, SMEM_DYN>>>();
    k_softmax<<<BATCH * LC, 256>>>();
    k_gemm_out<<<dim3(DIM / 128, LC / 128, BATCH), 256, SMEM_DYN>>>(out);
}